// round 13
// baseline (speedup 1.0000x reference)
#include <cuda_runtime.h>
#include <cuda_bf16.h>
#include <math.h>
#include <stddef.h>
#include <stdint.h>

#define L_   2
#define D_   1024
#define H_   16
#define HD_  64
#define DFF_ 4096
#define V_   32000
#define B_   2
#define S_   1024
#define N_   (B_*S_)   // 2048 tokens

typedef __nv_bfloat16 bf16;

// ---------------- device scratch (static, no allocations) ----------------
__device__ uint32_t g_embf8[(size_t)V_*D_/4];    // e4m3 x4 packed, scale 256
__device__ bf16  g_WqkvT[(size_t)L_*3*D_*D_];    // bf16 [l][3D][D]
__device__ bf16  g_WoT [(size_t)L_*D_*D_];       // bf16 [l][D][D]
__device__ uint32_t g_W18[(size_t)L_*DFF_*D_/4]; // e4m3 [l][DFF][D], scale 256
__device__ uint32_t g_W28[(size_t)L_*D_*DFF_/4]; // e4m3 [l][D][DFF], scale 256
__device__ float g_g1  [L_*D_];
__device__ float g_g2  [L_*D_];
__device__ float g_gfm [D_];
__device__ float g_x   [(size_t)N_*D_];
__device__ bf16  g_a   [(size_t)N_*D_];          // LN1 output (bf16)
__device__ uint32_t g_af8[(size_t)N_*D_/4];      // LN2/final-LN e4m3 x4, scale 4
__device__ bf16  g_qkvh[(size_t)N_*3*D_];
__device__ bf16  g_o   [(size_t)N_*D_];
__device__ uint32_t g_ff8[(size_t)N_*DFF_/4];    // GELU out e4m3, scale 16
__device__ float2 g_part[(size_t)N_*256];        // [token][nblock] lse partials
__device__ float g_tgt [N_];
__device__ float g_nll [N_];

// ---------------- helpers ----------------
__device__ __forceinline__ float warp_sum(float v){
    #pragma unroll
    for (int o=16;o;o>>=1) v += __shfl_down_sync(0xffffffffu, v, o);
    return v;
}
__device__ __forceinline__ float warp_max(float v){
    #pragma unroll
    for (int o=16;o;o>>=1) v = fmaxf(v, __shfl_down_sync(0xffffffffu, v, o));
    return v;
}
template<bool MAXRED>
__device__ __forceinline__ float block_reduce(float v){
    __shared__ float sh[8];
    int tid = threadIdx.x;
    v = MAXRED ? warp_max(v) : warp_sum(v);
    __syncthreads();
    if ((tid & 31) == 0) sh[tid>>5] = v;
    __syncthreads();
    if (tid < 32){
        float a = (tid < 8) ? sh[tid] : (MAXRED ? -3.402823e38f : 0.f);
        a = MAXRED ? warp_max(a) : warp_sum(a);
        if (tid == 0) sh[0] = a;
    }
    __syncthreads();
    return sh[0];
}
__device__ __forceinline__ float gelu_f(float x){
    float x3 = x*x*x;
    return 0.5f*x*(1.f + tanhf(0.7978845608028654f*(x + 0.044715f*x3)));
}
__device__ __forceinline__ uint32_t sptr(const void* p){
    return (uint32_t)__cvta_generic_to_shared(p);
}
__device__ __forceinline__ uint32_t pk2(float lo, float hi){
    uint32_t r;
    asm("cvt.rn.bf16x2.f32 %0, %1, %2;" : "=r"(r) : "f"(hi), "f"(lo));
    return r;
}
// pack 4 floats -> 4 e4m3 bytes, byte0 = v0
__device__ __forceinline__ uint32_t pk4_e4m3(float v0, float v1, float v2, float v3){
    uint16_t h0, h1;
    asm("cvt.rn.satfinite.e4m3x2.f32 %0, %1, %2;" : "=h"(h0) : "f"(v1), "f"(v0));
    asm("cvt.rn.satfinite.e4m3x2.f32 %0, %1, %2;" : "=h"(h1) : "f"(v3), "f"(v2));
    return (uint32_t)h0 | ((uint32_t)h1 << 16);
}

#define CP16(dst, src) \
    asm volatile("cp.async.cg.shared.global [%0], [%1], 16;\n" :: "r"(dst), "l"(src))
#define CP_COMMIT()  asm volatile("cp.async.commit_group;\n" ::)
#define CP_WAIT1()   asm volatile("cp.async.wait_group 1;\n" ::)

#define LDSM4(r0,r1,r2,r3,addr) \
    asm volatile("ldmatrix.sync.aligned.m8n8.x4.shared.b16 {%0,%1,%2,%3}, [%4];" \
                 : "=r"(r0), "=r"(r1), "=r"(r2), "=r"(r3) : "r"(addr))
#define LDSM4T(r0,r1,r2,r3,addr) \
    asm volatile("ldmatrix.sync.aligned.m8n8.x4.trans.shared.b16 {%0,%1,%2,%3}, [%4];" \
                 : "=r"(r0), "=r"(r1), "=r"(r2), "=r"(r3) : "r"(addr))
#define MMA16816(c0,c1,c2,c3,a0,a1,a2,a3,b0,b1) \
    asm volatile( \
        "mma.sync.aligned.m16n8k16.row.col.f32.bf16.bf16.f32 " \
        "{%0,%1,%2,%3}, {%4,%5,%6,%7}, {%8,%9}, {%0,%1,%2,%3};\n" \
        : "+f"(c0), "+f"(c1), "+f"(c2), "+f"(c3) \
        : "r"(a0), "r"(a1), "r"(a2), "r"(a3), "r"(b0), "r"(b1))
#define MMAF8(c0,c1,c2,c3,a0,a1,a2,a3,b0,b1) \
    asm volatile( \
        "mma.sync.aligned.m16n8k32.row.col.f32.e4m3.e4m3.f32 " \
        "{%0,%1,%2,%3}, {%4,%5,%6,%7}, {%8,%9}, {%0,%1,%2,%3};\n" \
        : "+f"(c0), "+f"(c1), "+f"(c2), "+f"(c3) \
        : "r"(a0), "r"(a1), "r"(a2), "r"(a3), "r"(b0), "r"(b1))

// ---------------- merge kernels ----------------
__global__ void merge_kernel(const float* __restrict__ base,
                             const float* __restrict__ delta,
                             const float* __restrict__ lam,
                             float* __restrict__ out, size_t n){
    size_t n4 = n >> 2;
    float l0 = lam[0], l1 = lam[1];
    const float4* b4 = (const float4*)base;
    const float4* d0 = (const float4*)delta;
    const float4* d1 = (const float4*)(delta + n);
    float4* o4 = (float4*)out;
    for (size_t i = (size_t)blockIdx.x*blockDim.x + threadIdx.x; i < n4;
         i += (size_t)gridDim.x*blockDim.x){
        float4 b = b4[i], x0 = d0[i], x1 = d1[i], r;
        r.x = b.x + l0*x0.x + l1*x1.x;
        r.y = b.y + l0*x0.y + l1*x1.y;
        r.z = b.z + l0*x0.z + l1*x1.z;
        r.w = b.w + l0*x0.w + l1*x1.w;
        o4[i] = r;
    }
}
// emb merge: e4m3 out only (logits GEMM, scale 256)
__global__ void merge_emb_f8(const float* __restrict__ base,
                             const float* __restrict__ delta,
                             const float* __restrict__ lam,
                             uint32_t* __restrict__ outf8, size_t n){
    size_t n4 = n >> 2;
    float l0 = lam[0], l1 = lam[1];
    const float4* b4 = (const float4*)base;
    const float4* d0 = (const float4*)delta;
    const float4* d1 = (const float4*)(delta + n);
    for (size_t i = (size_t)blockIdx.x*blockDim.x + threadIdx.x; i < n4;
         i += (size_t)gridDim.x*blockDim.x){
        float4 b = b4[i], x0 = d0[i], x1 = d1[i];
        float r0 = b.x + l0*x0.x + l1*x1.x;
        float r1 = b.y + l0*x0.y + l1*x1.y;
        float r2 = b.z + l0*x0.z + l1*x1.z;
        float r3 = b.w + l0*x0.w + l1*x1.w;
        outf8[i] = pk4_e4m3(r0*256.f, r1*256.f, r2*256.f, r3*256.f);
    }
}
// transpose-merge -> bf16
__global__ void tmerge_kernel(const float* __restrict__ base,
                              const float* __restrict__ delta,
                              const float* __restrict__ lam,
                              bf16* __restrict__ out,
                              int K, int Nw, size_t tstride){
    __shared__ float tile[32][33];
    int z = blockIdx.z;
    size_t mo = (size_t)z*K*Nw;
    float l0 = lam[0], l1 = lam[1];
    int n0 = blockIdx.x*32, k0 = blockIdx.y*32;
    #pragma unroll
    for (int j = 0; j < 32; j += 8){
        int k = k0 + threadIdx.y + j;
        int nn = n0 + threadIdx.x;
        size_t idx = mo + (size_t)k*Nw + nn;
        tile[threadIdx.y + j][threadIdx.x] =
            base[idx] + l0*delta[idx] + l1*delta[tstride + idx];
    }
    __syncthreads();
    #pragma unroll
    for (int j = 0; j < 32; j += 8){
        int nn = n0 + threadIdx.y + j;
        int k = k0 + threadIdx.x;
        out[mo + (size_t)nn*K + k] = __float2bfloat16(tile[threadIdx.x][threadIdx.y + j]);
    }
}
// transpose-merge -> packed e4m3 (x scale)
__global__ void tmerge_f8(const float* __restrict__ base,
                          const float* __restrict__ delta,
                          const float* __restrict__ lam,
                          uint32_t* __restrict__ out,
                          int K, int Nw, size_t tstride, float scale){
    __shared__ float tile[32][33];
    int z = blockIdx.z;
    size_t mo = (size_t)z*K*Nw;
    float l0 = lam[0], l1 = lam[1];
    int n0 = blockIdx.x*32, k0 = blockIdx.y*32;
    #pragma unroll
    for (int j = 0; j < 32; j += 8){
        int k = k0 + threadIdx.y + j;
        int nn = n0 + threadIdx.x;
        size_t idx = mo + (size_t)k*Nw + nn;
        tile[threadIdx.y + j][threadIdx.x] =
            base[idx] + l0*delta[idx] + l1*delta[tstride + idx];
    }
    __syncthreads();
    int tid = threadIdx.y*32 + threadIdx.x;
    int nn_l = tid >> 3;
    int kg = tid & 7;
    int nn = n0 + nn_l;
    int kk = kg*4;
    float v0 = tile[kk][nn_l]   * scale;
    float v1 = tile[kk+1][nn_l] * scale;
    float v2 = tile[kk+2][nn_l] * scale;
    float v3 = tile[kk+3][nn_l] * scale;
    out[((mo + (size_t)nn*K + k0) >> 2) + kg] = pk4_e4m3(v0, v1, v2, v3);
}

// ---------------- gather with on-the-fly merge ----------------
__global__ void gather_merge(const int* __restrict__ ids,
                             const float* __restrict__ emb,
                             const float* __restrict__ demb,
                             const float* __restrict__ lam,
                             float* __restrict__ x){
    int t = blockIdx.x;
    int id = ids[t];
    float l0 = lam[0], l1 = lam[1];
    const float4* b  = (const float4*)(emb  + (size_t)id*D_);
    const float4* e0 = (const float4*)(demb + (size_t)id*D_);
    const float4* e1 = (const float4*)(demb + (size_t)V_*D_ + (size_t)id*D_);
    float4* dst = (float4*)(x + (size_t)t*D_);
    for (int d = threadIdx.x; d < D_/4; d += blockDim.x){
        float4 bb = b[d], x0 = e0[d], x1 = e1[d], r;
        r.x = bb.x + l0*x0.x + l1*x1.x;
        r.y = bb.y + l0*x0.y + l1*x1.y;
        r.z = bb.z + l0*x0.z + l1*x1.z;
        r.w = bb.w + l0*x0.w + l1*x1.w;
        dst[d] = r;
    }
}

// ---------------- layernorm ----------------
__global__ void ln_kernel(const float* __restrict__ x,
                          const float* __restrict__ g,
                          bf16* __restrict__ out){
    int t = blockIdx.x;
    int tid = threadIdx.x;
    const float* xr = x + (size_t)t*D_;
    float s = 0.f, ss = 0.f;
    for (int d = tid; d < D_; d += 256){ float v = xr[d]; s += v; ss = fmaf(v, v, ss); }
    float tots = block_reduce<false>(s);
    float totss = block_reduce<false>(ss);
    float mu = tots * (1.f/D_);
    float var = totss * (1.f/D_) - mu*mu;
    float inv = rsqrtf(var + 1e-5f);
    bf16* orow = out + (size_t)t*D_;
    for (int d = tid; d < D_; d += 256)
        orow[d] = __float2bfloat16((xr[d]-mu)*inv*g[d]);
}
// LN -> e4m3 packed, scale 4
__global__ void ln_f8_kernel(const float* __restrict__ x,
                             const float* __restrict__ g,
                             uint32_t* __restrict__ out){
    int t = blockIdx.x;
    int tid = threadIdx.x;
    const float* xr = x + (size_t)t*D_;
    float s = 0.f, ss = 0.f;
    for (int d = tid; d < D_; d += 256){ float v = xr[d]; s += v; ss = fmaf(v, v, ss); }
    float tots = block_reduce<false>(s);
    float totss = block_reduce<false>(ss);
    float mu = tots * (1.f/D_);
    float var = totss * (1.f/D_) - mu*mu;
    float inv = rsqrtf(var + 1e-5f);
    int d = tid*4;
    float v0 = (xr[d]-mu)*inv*g[d]     * 4.f;
    float v1 = (xr[d+1]-mu)*inv*g[d+1] * 4.f;
    float v2 = (xr[d+2]-mu)*inv*g[d+2] * 4.f;
    float v3 = (xr[d+3]-mu)*inv*g[d+3] * 4.f;
    out[(size_t)t*(D_/4) + tid] = pk4_e4m3(v0, v1, v2, v3);
}

// ================= bf16 GEMM (NT, 2-stage cp.async + ldmatrix) ============
#define PAD 40

template<int ACT, int RES, int OUTBF>
__global__ void __launch_bounds__(256) hgemm(int M, int N, int K,
                        const bf16* __restrict__ A,
                        const bf16* __restrict__ Bt,
                        const float* __restrict__ Res,
                        void* __restrict__ Cout){
    __shared__ __align__(16) bf16 As[2][128*PAD];
    __shared__ __align__(16) bf16 Bs[2][128*PAD];

    const int tid  = threadIdx.x;
    const int lane = tid & 31;
    const int warp = tid >> 5;
    const int g    = lane >> 2;
    const int t    = lane & 3;
    const int wm   = warp >> 1;
    const int wn   = warp & 1;
    const int row0 = blockIdx.x * 128;
    const int col0 = blockIdx.y * 128;

    float c[2][8][4];
    #pragma unroll
    for (int i=0;i<2;i++)
        #pragma unroll
        for (int j=0;j<8;j++)
            #pragma unroll
            for (int k=0;k<4;k++) c[i][j][k]=0.f;

    const int r1 = tid >> 2;
    const int c8 = (tid & 3) * 8;
    const bf16* Ag0 = A  + (size_t)(row0 + r1)*K + c8;
    const bf16* Ag1 = A  + (size_t)(row0 + r1 + 64)*K + c8;
    const bf16* Bg0 = Bt + (size_t)(col0 + r1)*K + c8;
    const bf16* Bg1 = Bt + (size_t)(col0 + r1 + 64)*K + c8;
    const uint32_t sa0 = sptr(&As[0][r1*PAD + c8]);
    const uint32_t sa1 = sptr(&As[0][(r1+64)*PAD + c8]);
    const uint32_t sb0 = sptr(&Bs[0][r1*PAD + c8]);
    const uint32_t sb1 = sptr(&Bs[0][(r1+64)*PAD + c8]);
    const uint32_t SS = 128*PAD*2;

    uint32_t aAddr[2];
    #pragma unroll
    for (int mt = 0; mt < 2; mt++)
        aAddr[mt] = sptr(&As[0][(wm*32 + mt*16 + (lane & 15))*PAD + (lane >> 4)*8]);
    uint32_t bAddr[4];
    #pragma unroll
    for (int bt = 0; bt < 4; bt++)
        bAddr[bt] = sptr(&Bs[0][(wn*64 + bt*16 + ((lane>>4)&1)*8 + (lane&7))*PAD
                                + ((lane>>3)&1)*8]);

    {
        CP16(sa0, Ag0); CP16(sa1, Ag1);
        CP16(sb0, Bg0); CP16(sb1, Bg1);
        CP_COMMIT();
    }

    const int KT = K >> 5;
    int s = 0;
    for (int kt = 0; kt < KT; kt++){
        if (kt + 1 < KT){
            const int ko = (kt + 1) << 5;
            const uint32_t so = (s ^ 1) * SS;
            CP16(sa0 + so, Ag0 + ko); CP16(sa1 + so, Ag1 + ko);
            CP16(sb0 + so, Bg0 + ko); CP16(sb1 + so, Bg1 + ko);
        }
        CP_COMMIT();
        CP_WAIT1();
        __syncthreads();

        const uint32_t sb = s * SS;
        #pragma unroll
        for (int ks = 0; ks < 2; ks++){
            const uint32_t kb = sb + ks*32;
            uint32_t a[2][4];
            #pragma unroll
            for (int mt = 0; mt < 2; mt++)
                LDSM4(a[mt][0], a[mt][1], a[mt][2], a[mt][3], aAddr[mt] + kb);
            uint32_t bb[4][4];
            #pragma unroll
            for (int bt = 0; bt < 4; bt++)
                LDSM4(bb[bt][0], bb[bt][1], bb[bt][2], bb[bt][3], bAddr[bt] + kb);
            #pragma unroll
            for (int mt = 0; mt < 2; mt++)
                #pragma unroll
                for (int nt = 0; nt < 8; nt++){
                    const int bt = nt >> 1, su = (nt & 1) * 2;
                    MMA16816(c[mt][nt][0], c[mt][nt][1], c[mt][nt][2], c[mt][nt][3],
                             a[mt][0], a[mt][1], a[mt][2], a[mt][3],
                             bb[bt][su], bb[bt][su+1]);
                }
        }
        __syncthreads();
        s ^= 1;
    }

    float* Cf = (float*)Cout;
    bf16*  Ch = (bf16*)Cout;
    #pragma unroll
    for (int mt = 0; mt < 2; mt++){
        int r0 = row0 + wm*32 + mt*16 + g;
        #pragma unroll
        for (int nt = 0; nt < 8; nt++){
            int cc = col0 + wn*64 + nt*8 + 2*t;
            float v0 = c[mt][nt][0], v1 = c[mt][nt][1];
            float v2 = c[mt][nt][2], v3 = c[mt][nt][3];
            if (RES){
                v0 += Res[(size_t)r0*N + cc];
                v1 += Res[(size_t)r0*N + cc + 1];
                v2 += Res[(size_t)(r0+8)*N + cc];
                v3 += Res[(size_t)(r0+8)*N + cc + 1];
            }
            if (ACT){
                v0 = gelu_f(v0); v1 = gelu_f(v1);
                v2 = gelu_f(v2); v3 = gelu_f(v3);
            }
            if (OUTBF){
                *(__nv_bfloat162*)&Ch[(size_t)r0*N + cc]     = __floats2bfloat162_rn(v0, v1);
                *(__nv_bfloat162*)&Ch[(size_t)(r0+8)*N + cc] = __floats2bfloat162_rn(v2, v3);
            } else {
                Cf[(size_t)r0*N + cc]         = v0;
                Cf[(size_t)r0*N + cc + 1]     = v1;
                Cf[(size_t)(r0+8)*N + cc]     = v2;
                Cf[(size_t)(r0+8)*N + cc + 1] = v3;
            }
        }
    }
}

// ================= FP8 GEMM (2-stage, generic epilogue) ===================
// OUT: 0 = fp32 (+Res), 2 = packed e4m3 (x osc)
template<int ACT, int RES, int OUT>
__global__ void __launch_bounds__(256) f8gemm(int K16, int N,
                        const bf16* __restrict__ A,
                        const bf16* __restrict__ Bt,
                        const float* __restrict__ Res,
                        void* __restrict__ Cout,
                        float dsc, float osc){
    __shared__ __align__(16) bf16 As[2][128*PAD];
    __shared__ __align__(16) bf16 Bs[2][128*PAD];

    const int tid  = threadIdx.x;
    const int lane = tid & 31;
    const int warp = tid >> 5;
    const int g    = lane >> 2;
    const int t    = lane & 3;
    const int wm   = warp >> 1;
    const int wn   = warp & 1;
    const int row0 = blockIdx.x * 128;
    const int col0 = blockIdx.y * 128;
    const int K = K16;

    float c[2][8][4];
    #pragma unroll
    for (int i=0;i<2;i++)
        #pragma unroll
        for (int j=0;j<8;j++)
            #pragma unroll
            for (int k=0;k<4;k++) c[i][j][k]=0.f;

    const int r1 = tid >> 2;
    const int c8 = (tid & 3) * 8;
    const bf16* Ag0 = A  + (size_t)(row0 + r1)*K + c8;
    const bf16* Ag1 = A  + (size_t)(row0 + r1 + 64)*K + c8;
    const bf16* Bg0 = Bt + (size_t)(col0 + r1)*K + c8;
    const bf16* Bg1 = Bt + (size_t)(col0 + r1 + 64)*K + c8;
    const uint32_t sa0 = sptr(&As[0][r1*PAD + c8]);
    const uint32_t sa1 = sptr(&As[0][(r1+64)*PAD + c8]);
    const uint32_t sb0 = sptr(&Bs[0][r1*PAD + c8]);
    const uint32_t sb1 = sptr(&Bs[0][(r1+64)*PAD + c8]);
    const uint32_t SS = 128*PAD*2;

    uint32_t aAddr[2];
    #pragma unroll
    for (int mt = 0; mt < 2; mt++)
        aAddr[mt] = sptr(&As[0][(wm*32 + mt*16 + (lane & 15))*PAD + (lane >> 4)*8]);
    uint32_t bAddr[4];
    #pragma unroll
    for (int bt = 0; bt < 4; bt++)
        bAddr[bt] = sptr(&Bs[0][(wn*64 + bt*16 + ((lane>>4)&1)*8 + (lane&7))*PAD
                                + ((lane>>3)&1)*8]);

    {
        CP16(sa0, Ag0); CP16(sa1, Ag1);
        CP16(sb0, Bg0); CP16(sb1, Bg1);
        CP_COMMIT();
    }

    const int KT = K >> 5;
    int s = 0;
    for (int kt = 0; kt < KT; kt++){
        if (kt + 1 < KT){
            const int ko = (kt + 1) << 5;
            const uint32_t so = (s ^ 1) * SS;
            CP16(sa0 + so, Ag0 + ko); CP16(sa1 + so, Ag1 + ko);
            CP16(sb0 + so, Bg0 + ko); CP16(sb1 + so, Bg1 + ko);
        }
        CP_COMMIT();
        CP_WAIT1();
        __syncthreads();

        const uint32_t sb = s * SS;
        #pragma unroll
        for (int ks = 0; ks < 2; ks++){
            const uint32_t kb = sb + ks*32;
            uint32_t a[2][4];
            #pragma unroll
            for (int mt = 0; mt < 2; mt++)
                LDSM4(a[mt][0], a[mt][1], a[mt][2], a[mt][3], aAddr[mt] + kb);
            uint32_t bb[4][4];
            #pragma unroll
            for (int bt = 0; bt < 4; bt++)
                LDSM4(bb[bt][0], bb[bt][1], bb[bt][2], bb[bt][3], bAddr[bt] + kb);
            #pragma unroll
            for (int mt = 0; mt < 2; mt++)
                #pragma unroll
                for (int nt = 0; nt < 8; nt++){
                    const int bt = nt >> 1, su = (nt & 1) * 2;
                    MMAF8(c[mt][nt][0], c[mt][nt][1], c[mt][nt][2], c[mt][nt][3],
                          a[mt][0], a[mt][1], a[mt][2], a[mt][3],
                          bb[bt][su], bb[bt][su+1]);
                }
        }
        __syncthreads();
        s ^= 1;
    }

    float* Cf = (float*)Cout;
    uint32_t* C8 = (uint32_t*)Cout;
    #pragma unroll
    for (int mt = 0; mt < 2; mt++){
        int r0 = row0 + wm*32 + mt*16 + g;
        #pragma unroll
        for (int nt = 0; nt < 8; nt++){
            int cc = col0 + wn*64 + nt*8 + 2*t;
            float v0 = c[mt][nt][0]*dsc, v1 = c[mt][nt][1]*dsc;
            float v2 = c[mt][nt][2]*dsc, v3 = c[mt][nt][3]*dsc;
            if (RES){
                v0 += Res[(size_t)r0*N + cc];
                v1 += Res[(size_t)r0*N + cc + 1];
                v2 += Res[(size_t)(r0+8)*N + cc];
                v3 += Res[(size_t)(r0+8)*N + cc + 1];
            }
            if (ACT){
                v0 = gelu_f(v0); v1 = gelu_f(v1);
                v2 = gelu_f(v2); v3 = gelu_f(v3);
            }
            if (OUT == 2){
                v0 *= osc; v1 *= osc; v2 *= osc; v3 *= osc;
                float u0 = __shfl_xor_sync(0xffffffffu, v0, 1);
                float u1 = __shfl_xor_sync(0xffffffffu, v1, 1);
                float u2 = __shfl_xor_sync(0xffffffffu, v2, 1);
                float u3 = __shfl_xor_sync(0xffffffffu, v3, 1);
                if ((t & 1) == 0){
                    size_t i0 = ((size_t)r0*N + cc) >> 2;
                    size_t i1 = ((size_t)(r0+8)*N + cc) >> 2;
                    C8[i0] = pk4_e4m3(v0, v1, u0, u1);
                    C8[i1] = pk4_e4m3(v2, v3, u2, u3);
                }
            } else {
                Cf[(size_t)r0*N + cc]         = v0;
                Cf[(size_t)r0*N + cc + 1]     = v1;
                Cf[(size_t)(r0+8)*N + cc]     = v2;
                Cf[(size_t)(r0+8)*N + cc + 1] = v3;
            }
        }
    }
}

// ============ FP8 logits GEMM (2-stage) with fused logsumexp ==============
__global__ void __launch_bounds__(256) f8gemm_lse(int K16,
                        const bf16* __restrict__ A,
                        const bf16* __restrict__ Bt,
                        const int* __restrict__ labels,
                        float2* __restrict__ part,
                        float* __restrict__ tgtlog){
    __shared__ __align__(16) bf16 As[2][128*PAD];
    __shared__ __align__(16) bf16 Bs[2][128*PAD];
    __shared__ float2 red[2][128];
    __shared__ float  tgv[2][128];
    __shared__ float  tgf[2][128];

    const int tid  = threadIdx.x;
    const int lane = tid & 31;
    const int warp = tid >> 5;
    const int g    = lane >> 2;
    const int t    = lane & 3;
    const int wm   = warp >> 1;
    const int wn   = warp & 1;
    const int row0 = blockIdx.x * 128;
    const int col0 = blockIdx.y * 128;
    const int K = K16;

    float c[2][8][4];
    #pragma unroll
    for (int i=0;i<2;i++)
        #pragma unroll
        for (int j=0;j<8;j++)
            #pragma unroll
            for (int k=0;k<4;k++) c[i][j][k]=0.f;

    const int r1 = tid >> 2;
    const int c8 = (tid & 3) * 8;
    const bf16* Ag0 = A  + (size_t)(row0 + r1)*K + c8;
    const bf16* Ag1 = A  + (size_t)(row0 + r1 + 64)*K + c8;
    const bf16* Bg0 = Bt + (size_t)(col0 + r1)*K + c8;
    const bf16* Bg1 = Bt + (size_t)(col0 + r1 + 64)*K + c8;
    const uint32_t sa0 = sptr(&As[0][r1*PAD + c8]);
    const uint32_t sa1 = sptr(&As[0][(r1+64)*PAD + c8]);
    const uint32_t sb0 = sptr(&Bs[0][r1*PAD + c8]);
    const uint32_t sb1 = sptr(&Bs[0][(r1+64)*PAD + c8]);
    const uint32_t SS = 128*PAD*2;

    uint32_t aAddr[2];
    #pragma unroll
    for (int mt = 0; mt < 2; mt++)
        aAddr[mt] = sptr(&As[0][(wm*32 + mt*16 + (lane & 15))*PAD + (lane >> 4)*8]);
    uint32_t bAddr[4];
    #pragma unroll
    for (int bt = 0; bt < 4; bt++)
        bAddr[bt] = sptr(&Bs[0][(wn*64 + bt*16 + ((lane>>4)&1)*8 + (lane&7))*PAD
                                + ((lane>>3)&1)*8]);

    {
        CP16(sa0, Ag0); CP16(sa1, Ag1);
        CP16(sb0, Bg0); CP16(sb1, Bg1);
        CP_COMMIT();
    }

    const int KT = K >> 5;
    int s = 0;
    for (int kt = 0; kt < KT; kt++){
        if (kt + 1 < KT){
            const int ko = (kt + 1) << 5;
            const uint32_t so = (s ^ 1) * SS;
            CP16(sa0 + so, Ag0 + ko); CP16(sa1 + so, Ag1 + ko);
            CP16(sb0 + so, Bg0 + ko); CP16(sb1 + so, Bg1 + ko);
        }
        CP_COMMIT();
        CP_WAIT1();
        __syncthreads();

        const uint32_t sb = s * SS;
        #pragma unroll
        for (int ks = 0; ks < 2; ks++){
            const uint32_t kb = sb + ks*32;
            uint32_t a[2][4];
            #pragma unroll
            for (int mt = 0; mt < 2; mt++)
                LDSM4(a[mt][0], a[mt][1], a[mt][2], a[mt][3], aAddr[mt] + kb);
            uint32_t bb[4][4];
            #pragma unroll
            for (int bt = 0; bt < 4; bt++)
                LDSM4(bb[bt][0], bb[bt][1], bb[bt][2], bb[bt][3], bAddr[bt] + kb);
            #pragma unroll
            for (int mt = 0; mt < 2; mt++)
                #pragma unroll
                for (int nt = 0; nt < 8; nt++){
                    const int bt = nt >> 1, su = (nt & 1) * 2;
                    MMAF8(c[mt][nt][0], c[mt][nt][1], c[mt][nt][2], c[mt][nt][3],
                          a[mt][0], a[mt][1], a[mt][2], a[mt][3],
                          bb[bt][su], bb[bt][su+1]);
                }
        }
        __syncthreads();
        s ^= 1;
    }

    const float scale = 1.f/1024.f;
    #pragma unroll
    for (int mt = 0; mt < 2; mt++){
        #pragma unroll
        for (int half = 0; half < 2; half++){
            const int rowi = wm*32 + mt*16 + half*8 + g;
            const int token = row0 + rowi;
            const int ss2 = token & (S_-1);
            const int tgt = (ss2 == S_-1) ? -1
                          : labels[(token >> 10)*S_ + ss2 + 1];
            float rm = -1e30f;
            float v[16];
            #pragma unroll
            for (int nt = 0; nt < 8; nt++){
                v[2*nt]   = c[mt][nt][2*half]   * scale;
                v[2*nt+1] = c[mt][nt][2*half+1] * scale;
                rm = fmaxf(rm, fmaxf(v[2*nt], v[2*nt+1]));
            }
            float rs = 0.f, tv = 0.f, tf = 0.f;
            #pragma unroll
            for (int nt = 0; nt < 8; nt++){
                rs += __expf(v[2*nt] - rm) + __expf(v[2*nt+1] - rm);
                int col = col0 + wn*64 + nt*8 + 2*t;
                if (col   == tgt){ tv = v[2*nt];   tf = 1.f; }
                if (col+1 == tgt){ tv = v[2*nt+1]; tf = 1.f; }
            }
            #pragma unroll
            for (int o = 1; o <= 2; o <<= 1){
                float om = __shfl_xor_sync(0xffffffffu, rm, o);
                float os = __shfl_xor_sync(0xffffffffu, rs, o);
                float nm = fmaxf(rm, om);
                rs = rs*__expf(rm - nm) + os*__expf(om - nm);
                rm = nm;
                tv += __shfl_xor_sync(0xffffffffu, tv, o);
                tf += __shfl_xor_sync(0xffffffffu, tf, o);
            }
            if (t == 0){
                red[wn][rowi] = make_float2(rm, rs);
                tgv[wn][rowi] = tv;
                tgf[wn][rowi] = tf;
            }
        }
    }
    __syncthreads();
    if (tid < 128){
        float2 p0 = red[0][tid], p1 = red[1][tid];
        float m = fmaxf(p0.x, p1.x);
        float sm = p0.y*__expf(p0.x - m) + p1.y*__expf(p1.x - m);
        int token = row0 + tid;
        part[(size_t)token*256 + blockIdx.y] = make_float2(m, sm);
        if (tgf[0][tid] + tgf[1][tid] > 0.5f)
            tgtlog[token] = tgv[0][tid] + tgv[1][tid];
    }
}

// ================= fused flash attention ==================================
#define QPAD 72

__global__ void __launch_bounds__(256) flash_attn(const bf16* __restrict__ qkv,
                                                  bf16* __restrict__ out){
    __shared__ __align__(16) bf16 Qs[128*QPAD];
    __shared__ __align__(16) bf16 Ks[2][64*QPAD];
    __shared__ __align__(16) bf16 Vs[2][64*QPAD];

    const int tid  = threadIdx.x;
    const int lane = tid & 31;
    const int warp = tid >> 5;
    const int g    = lane >> 2;
    const int t    = lane & 3;
    const int qt   = blockIdx.x;
    const int bh   = blockIdx.y;
    const int b    = bh >> 4, h = bh & 15;
    const int q0   = qt * 128;

    const size_t tok0 = (size_t)b * S_;
    const bf16* Qg = qkv + (tok0 + q0)*(3*D_) + h*HD_;
    const bf16* Kg = qkv + tok0*(3*D_) + D_   + h*HD_;
    const bf16* Vg = qkv + tok0*(3*D_) + 2*D_ + h*HD_;

    {
        #pragma unroll
        for (int j = 0; j < 4; j++){
            int ch = tid + j*256;
            int r = ch >> 3, c = (ch & 7)*8;
            CP16(sptr(&Qs[r*QPAD + c]), Qg + (size_t)r*(3*D_) + c);
        }
        #pragma unroll
        for (int j = 0; j < 2; j++){
            int ch = tid + j*256;
            int r = ch >> 3, c = (ch & 7)*8;
            CP16(sptr(&Ks[0][r*QPAD + c]), Kg + (size_t)r*(3*D_) + c);
            CP16(sptr(&Vs[0][r*QPAD + c]), Vg + (size_t)r*(3*D_) + c);
        }
        CP_COMMIT();
    }

    float m0 = -1e30f, m1 = -1e30f, l0 = 0.f, l1 = 0.f;
    float o[8][4];
    #pragma unroll
    for (int i=0;i<8;i++){ o[i][0]=0.f; o[i][1]=0.f; o[i][2]=0.f; o[i][3]=0.f; }

    const uint32_t aQ = sptr(&Qs[(warp*16 + (lane & 15))*QPAD + (lane >> 4)*8]);
    uint32_t kA[4], vA[4];
    #pragma unroll
    for (int bt = 0; bt < 4; bt++)
        kA[bt] = sptr(&Ks[0][(bt*16 + ((lane>>4)&1)*8 + (lane&7))*QPAD
                             + ((lane>>3)&1)*8]);
    #pragma unroll
    for (int dt = 0; dt < 4; dt++)
        vA[dt] = sptr(&Vs[0][(((lane>>3)&1)*8 + (lane&7))*QPAD
                             + dt*16 + ((lane>>4)&1)*8]);
    const uint32_t KVS = 64*QPAD*2;

    const int nkt = 2*qt + 2;
    int s = 0;
    for (int kt = 0; kt < nkt; kt++){
        if (kt + 1 < nkt){
            const bf16* Kg2 = Kg + (size_t)(kt+1)*64*(3*D_);
            const bf16* Vg2 = Vg + (size_t)(kt+1)*64*(3*D_);
            bf16* ksm = &Ks[s^1][0];
            bf16* vsm = &Vs[s^1][0];
            #pragma unroll
            for (int j = 0; j < 2; j++){
                int ch = tid + j*256;
                int r = ch >> 3, c = (ch & 7)*8;
                CP16(sptr(ksm + r*QPAD + c), Kg2 + (size_t)r*(3*D_) + c);
                CP16(sptr(vsm + r*QPAD + c), Vg2 + (size_t)r*(3*D_) + c);
            }
        }
        CP_COMMIT();
        CP_WAIT1();
        __syncthreads();

        const uint32_t so = s * KVS;

        float sc[8][4];
        #pragma unroll
        for (int i=0;i<8;i++){ sc[i][0]=0.f; sc[i][1]=0.f; sc[i][2]=0.f; sc[i][3]=0.f; }
        #pragma unroll
        for (int kk = 0; kk < 4; kk++){
            uint32_t a0,a1,a2,a3;
            LDSM4(a0,a1,a2,a3, aQ + kk*32);
            uint32_t bb[4][4];
            #pragma unroll
            for (int bt = 0; bt < 4; bt++)
                LDSM4(bb[bt][0],bb[bt][1],bb[bt][2],bb[bt][3], kA[bt] + so + kk*32);
            #pragma unroll
            for (int nt = 0; nt < 8; nt++){
                const int bt = nt >> 1, su = (nt & 1)*2;
                MMA16816(sc[nt][0],sc[nt][1],sc[nt][2],sc[nt][3],
                         a0,a1,a2,a3, bb[bt][su], bb[bt][su+1]);
            }
        }

        const int qrow0 = q0 + warp*16 + g;
        const int qrow1 = qrow0 + 8;
        const bool masked = (kt >= 2*qt);
        #pragma unroll
        for (int nt = 0; nt < 8; nt++){
            int col = kt*64 + nt*8 + 2*t;
            #pragma unroll
            for (int u = 0; u < 4; u++) sc[nt][u] *= 0.125f;
            if (masked){
                if (col   > qrow0) sc[nt][0] = -1e30f;
                if (col+1 > qrow0) sc[nt][1] = -1e30f;
                if (col   > qrow1) sc[nt][2] = -1e30f;
                if (col+1 > qrow1) sc[nt][3] = -1e30f;
            }
        }

        float tm0 = -1e30f, tm1 = -1e30f;
        #pragma unroll
        for (int nt = 0; nt < 8; nt++){
            tm0 = fmaxf(tm0, fmaxf(sc[nt][0], sc[nt][1]));
            tm1 = fmaxf(tm1, fmaxf(sc[nt][2], sc[nt][3]));
        }
        tm0 = fmaxf(tm0, __shfl_xor_sync(0xffffffffu, tm0, 1));
        tm0 = fmaxf(tm0, __shfl_xor_sync(0xffffffffu, tm0, 2));
        tm1 = fmaxf(tm1, __shfl_xor_sync(0xffffffffu, tm1, 1));
        tm1 = fmaxf(tm1, __shfl_xor_sync(0xffffffffu, tm1, 2));
        float nm0 = fmaxf(m0, tm0), nm1 = fmaxf(m1, tm1);
        float al0 = __expf(m0 - nm0), al1 = __expf(m1 - nm1);
        m0 = nm0; m1 = nm1;
        float ps0 = 0.f, ps1 = 0.f;
        #pragma unroll
        for (int nt = 0; nt < 8; nt++){
            sc[nt][0] = __expf(sc[nt][0] - nm0);
            sc[nt][1] = __expf(sc[nt][1] - nm0);
            sc[nt][2] = __expf(sc[nt][2] - nm1);
            sc[nt][3] = __expf(sc[nt][3] - nm1);
            ps0 += sc[nt][0] + sc[nt][1];
            ps1 += sc[nt][2] + sc[nt][3];
        }
        l0 = l0*al0 + ps0;
        l1 = l1*al1 + ps1;
        #pragma unroll
        for (int dt = 0; dt < 8; dt++){
            o[dt][0] *= al0; o[dt][1] *= al0;
            o[dt][2] *= al1; o[dt][3] *= al1;
        }

        #pragma unroll
        for (int kk = 0; kk < 4; kk++){
            uint32_t a0 = pk2(sc[2*kk][0],   sc[2*kk][1]);
            uint32_t a1 = pk2(sc[2*kk][2],   sc[2*kk][3]);
            uint32_t a2 = pk2(sc[2*kk+1][0], sc[2*kk+1][1]);
            uint32_t a3 = pk2(sc[2*kk+1][2], sc[2*kk+1][3]);
            uint32_t vv[4][4];
            #pragma unroll
            for (int dt = 0; dt < 4; dt++)
                LDSM4T(vv[dt][0],vv[dt][1],vv[dt][2],vv[dt][3],
                       vA[dt] + so + kk*16*QPAD*2);
            #pragma unroll
            for (int nt = 0; nt < 8; nt++){
                const int dt = nt >> 1, su = (nt & 1)*2;
                MMA16816(o[nt][0],o[nt][1],o[nt][2],o[nt][3],
                         a0,a1,a2,a3, vv[dt][su], vv[dt][su+1]);
            }
        }
        __syncthreads();
        s ^= 1;
    }

    l0 += __shfl_xor_sync(0xffffffffu, l0, 1);
    l0 += __shfl_xor_sync(0xffffffffu, l0, 2);
    l1 += __shfl_xor_sync(0xffffffffu, l1, 1);
    l1 += __shfl_xor_sync(0xffffffffu, l1, 2);
    float r0 = 1.f/l0, r1 = 1.f/l1;
    const int row0 = q0 + warp*16 + g;
    bf16* O0 = out + (tok0 + row0)*D_ + h*HD_;
    bf16* O1 = out + (tok0 + row0 + 8)*D_ + h*HD_;
    #pragma unroll
    for (int dt = 0; dt < 8; dt++){
        int cc = dt*8 + 2*t;
        *(__nv_bfloat162*)&O0[cc] = __floats2bfloat162_rn(o[dt][0]*r0, o[dt][1]*r0);
        *(__nv_bfloat162*)&O1[cc] = __floats2bfloat162_rn(o[dt][2]*r1, o[dt][3]*r1);
    }
}

// ---------------- NLL final ----------------
__global__ void nll_final(const float2* __restrict__ part,
                          const float* __restrict__ tgtlog,
                          float* __restrict__ nll){
    int t = blockIdx.x, tid = threadIdx.x;
    int ss = t & (S_-1);
    if (ss == S_-1){ if (tid == 0) nll[t] = 0.f; return; }
    float2 p = (tid < V_/128) ? part[(size_t)t*256 + tid]
                              : make_float2(-1e30f, 0.f);
    float M = block_reduce<true>(p.x);
    float S = block_reduce<false>(p.y * __expf(p.x - M));
    if (tid == 0) nll[t] = logf(S) + M - tgtlog[t];
}

// ---------------- final mean ----------------
__global__ void final_reduce(const float* __restrict__ nll, float* __restrict__ out){
    float s = 0.f;
    for (int t = threadIdx.x; t < N_; t += 256)
        if ((t & (S_-1)) != S_-1) s += nll[t];
    s = block_reduce<false>(s);
    if (threadIdx.x == 0) out[0] = s * (1.f/(B_*(S_-1)));
}

// ---------------- side stream (created at static init) ----------------
struct SideStream {
    cudaStream_t s2;
    cudaEvent_t fork, join, join2;
    SideStream(){
        cudaStreamCreateWithFlags(&s2, cudaStreamNonBlocking);
        cudaEventCreateWithFlags(&fork,  cudaEventDisableTiming);
        cudaEventCreateWithFlags(&join,  cudaEventDisableTiming);
        cudaEventCreateWithFlags(&join2, cudaEventDisableTiming);
    }
};
static SideStream g_ss;

// ---------------- host launch ----------------
static inline int mgrid(size_t n){
    size_t n4 = n >> 2;
    return (int)((n4 + 255) / 256);
}

extern "C" void kernel_launch(void* const* d_in, const int* in_sizes, int n_in,
                              void* d_out, int out_size){
    const int*   ids    = (const int*)  d_in[0];
    const int*   labels = (const int*)  d_in[1];
    const float* lam    = (const float*)d_in[2];
    const float* emb    = (const float*)d_in[3];
    const float* Wqkv   = (const float*)d_in[4];
    const float* Wo     = (const float*)d_in[5];
    const float* W1     = (const float*)d_in[6];
    const float* W2     = (const float*)d_in[7];
    const float* g1     = (const float*)d_in[8];
    const float* g2     = (const float*)d_in[9];
    const float* gf     = (const float*)d_in[10];
    const float* d_emb  = (const float*)d_in[11];
    const float* d_Wqkv = (const float*)d_in[12];
    const float* d_Wo   = (const float*)d_in[13];
    const float* d_W1   = (const float*)d_in[14];
    const float* d_W2   = (const float*)d_in[15];
    const float* d_g1   = (const float*)d_in[16];
    const float* d_g2   = (const float*)d_in[17];
    const float* d_gf   = (const float*)d_in[18];

    float *p_g1, *p_g2, *p_gf, *p_x, *p_tgt, *p_nll;
    bf16  *p_WqkvT, *p_WoT, *p_a, *p_o, *p_qkvh;
    uint32_t *p_embf8, *p_af8, *p_W18, *p_W28, *p_ff8;
    float2 *p_part;
    cudaGetSymbolAddress((void**)&p_embf8,  g_embf8);
    cudaGetSymbolAddress((void**)&p_WqkvT,  g_WqkvT);
    cudaGetSymbolAddress((void**)&p_WoT,    g_WoT);
    cudaGetSymbolAddress((void**)&p_W18,    g_W18);
    cudaGetSymbolAddress((void**)&p_W28,    g_W28);
    cudaGetSymbolAddress((void**)&p_g1,     g_g1);
    cudaGetSymbolAddress((void**)&p_g2,     g_g2);
    cudaGetSymbolAddress((void**)&p_gf,     g_gfm);
    cudaGetSymbolAddress((void**)&p_x,      g_x);
    cudaGetSymbolAddress((void**)&p_a,      g_a);
    cudaGetSymbolAddress((void**)&p_af8,    g_af8);
    cudaGetSymbolAddress((void**)&p_qkvh,   g_qkvh);
    cudaGetSymbolAddress((void**)&p_o,      g_o);
    cudaGetSymbolAddress((void**)&p_ff8,    g_ff8);
    cudaGetSymbolAddress((void**)&p_part,   g_part);
    cudaGetSymbolAddress((void**)&p_tgt,    g_tgt);
    cudaGetSymbolAddress((void**)&p_nll,    g_nll);

    size_t n;
    dim3 t328(32, 8);

    // ---- fork: side stream runs BW-bound merges that are needed late.
    //      join (W merges) gates layer-0 Wo GEMM; join2 (emb) gates the
    //      head logits GEMM — giving the 65us emb merge an ~800us window
    //      to hide under the mma-bound layer GEMMs.
    cudaEventRecord(g_ss.fork, 0);
    cudaStreamWaitEvent(g_ss.s2, g_ss.fork, 0);
    tmerge_kernel<<<dim3(D_/32, D_/32, L_), t328, 0, g_ss.s2>>>(
        Wo, d_Wo, lam, p_WoT, D_, D_, (size_t)L_*D_*D_);
    tmerge_f8<<<dim3(DFF_/32, D_/32, L_), t328, 0, g_ss.s2>>>(
        W1, d_W1, lam, p_W18, D_, DFF_, (size_t)L_*D_*DFF_, 256.f);
    tmerge_f8<<<dim3(D_/32, DFF_/32, L_), t328, 0, g_ss.s2>>>(
        W2, d_W2, lam, p_W28, DFF_, D_, (size_t)L_*DFF_*D_, 256.f);
    cudaEventRecord(g_ss.join, g_ss.s2);
    n = (size_t)V_*D_;
    merge_emb_f8<<<mgrid(n),256,0,g_ss.s2>>>(emb, d_emb, lam, p_embf8, n);
    cudaEventRecord(g_ss.join2, g_ss.s2);

    // ---- main stream: what layer 0's prefix needs ----
    gather_merge<<<N_, 256>>>(ids, emb, d_emb, lam, p_x);
    n = (size_t)L_*D_;
    merge_kernel<<<mgrid(n),256>>>(g1, d_g1, lam, p_g1, n);
    merge_kernel<<<mgrid(n),256>>>(g2, d_g2, lam, p_g2, n);
    n = (size_t)D_;
    merge_kernel<<<mgrid(n),256>>>(gf, d_gf, lam, p_gf, n);
    tmerge_kernel<<<dim3(3*D_/32, D_/32, L_), t328>>>(Wqkv, d_Wqkv, lam, p_WqkvT,
                     D_, 3*D_, (size_t)L_*D_*3*D_);

    for (int l = 0; l < L_; l++){
        // attn (bf16 path)
        ln_kernel<<<N_,256>>>(p_x, p_g1 + l*D_, p_a);
        hgemm<0,0,1><<<dim3(N_/128, 3*D_/128), 256>>>(N_, 3*D_, D_, p_a,
                         p_WqkvT + (size_t)l*3*D_*D_, nullptr, p_qkvh);
        flash_attn<<<dim3(S_/128, B_*H_), 256>>>(p_qkvh, p_o);
        if (l == 0) cudaStreamWaitEvent(0, g_ss.join, 0);   // W merges ready
        hgemm<0,1,0><<<dim3(N_/128, D_/128), 256>>>(N_, D_, D_, p_o,
                         p_WoT + (size_t)l*D_*D_, p_x, p_x);
        // ffn (fp8 path)
        ln_f8_kernel<<<N_,256>>>(p_x, p_g2 + l*D_, p_af8);
        f8gemm<1,0,2><<<dim3(N_/128, DFF_/128), 256>>>(D_/2, DFF_,
            (const bf16*)p_af8, (const bf16*)(p_W18 + (size_t)l*DFF_*D_/4),
            nullptr, p_ff8, 1.f/1024.f, 16.f);
        f8gemm<0,1,0><<<dim3(N_/128, D_/128), 256>>>(DFF_/2, D_,
            (const bf16*)p_ff8, (const bf16*)(p_W28 + (size_t)l*D_*DFF_/4),
            p_x, p_x, 1.f/4096.f, 1.f);
    }

    // ---- head: fp8 logits GEMM with fused logsumexp ----
    ln_f8_kernel<<<N_,256>>>(p_x, p_gf, p_af8);
    cudaStreamWaitEvent(0, g_ss.join2, 0);                  // emb merge ready
    f8gemm_lse<<<dim3(N_/128, V_/128), 256>>>(D_/2,
        (const bf16*)p_af8, (const bf16*)p_embf8, labels, p_part, p_tgt);
    nll_final<<<N_,256>>>(p_part, p_tgt, p_nll);
    final_reduce<<<1,256>>>(p_nll, (float*)d_out);
}

// round 14
// speedup vs baseline: 1.0020x; 1.0020x over previous
#include <cuda_runtime.h>
#include <cuda_bf16.h>
#include <math.h>
#include <stddef.h>
#include <stdint.h>

#define L_   2
#define D_   1024
#define H_   16
#define HD_  64
#define DFF_ 4096
#define V_   32000
#define B_   2
#define S_   1024
#define N_   (B_*S_)   // 2048 tokens

typedef __nv_bfloat16 bf16;

// ---------------- device scratch (static, no allocations) ----------------
__device__ uint32_t g_embf8[(size_t)V_*D_/4];    // e4m3 x4 packed, scale 256
__device__ bf16  g_WqkvT[(size_t)L_*3*D_*D_];    // bf16 [l][3D][D]
__device__ bf16  g_WoT [(size_t)L_*D_*D_];       // bf16 [l][D][D]
__device__ uint32_t g_W18[(size_t)L_*DFF_*D_/4]; // e4m3 [l][DFF][D], scale 256
__device__ uint32_t g_W28[(size_t)L_*D_*DFF_/4]; // e4m3 [l][D][DFF], scale 256
__device__ float g_g1  [L_*D_];
__device__ float g_g2  [L_*D_];
__device__ float g_gfm [D_];
__device__ float g_x   [(size_t)N_*D_];
__device__ bf16  g_a   [(size_t)N_*D_];          // LN1 output (bf16)
__device__ uint32_t g_af8[(size_t)N_*D_/4];      // LN2/final-LN e4m3 x4, scale 4
__device__ bf16  g_qkvh[(size_t)N_*3*D_];
__device__ bf16  g_o   [(size_t)N_*D_];
__device__ uint32_t g_ff8[(size_t)N_*DFF_/4];    // GELU out e4m3, scale 16
__device__ float2 g_part[(size_t)N_*256];        // [token][nblock] lse partials
__device__ float g_tgt [N_];
__device__ float g_nll [N_];

// ---------------- helpers ----------------
__device__ __forceinline__ float warp_sum(float v){
    #pragma unroll
    for (int o=16;o;o>>=1) v += __shfl_down_sync(0xffffffffu, v, o);
    return v;
}
__device__ __forceinline__ float warp_max(float v){
    #pragma unroll
    for (int o=16;o;o>>=1) v = fmaxf(v, __shfl_down_sync(0xffffffffu, v, o));
    return v;
}
template<bool MAXRED>
__device__ __forceinline__ float block_reduce(float v){
    __shared__ float sh[8];
    int tid = threadIdx.x;
    v = MAXRED ? warp_max(v) : warp_sum(v);
    __syncthreads();
    if ((tid & 31) == 0) sh[tid>>5] = v;
    __syncthreads();
    if (tid < 32){
        float a = (tid < 8) ? sh[tid] : (MAXRED ? -3.402823e38f : 0.f);
        a = MAXRED ? warp_max(a) : warp_sum(a);
        if (tid == 0) sh[0] = a;
    }
    __syncthreads();
    return sh[0];
}
__device__ __forceinline__ float gelu_f(float x){
    float x3 = x*x*x;
    return 0.5f*x*(1.f + tanhf(0.7978845608028654f*(x + 0.044715f*x3)));
}
__device__ __forceinline__ uint32_t sptr(const void* p){
    return (uint32_t)__cvta_generic_to_shared(p);
}
__device__ __forceinline__ uint32_t pk2(float lo, float hi){
    uint32_t r;
    asm("cvt.rn.bf16x2.f32 %0, %1, %2;" : "=r"(r) : "f"(hi), "f"(lo));
    return r;
}
// pack 4 floats -> 4 e4m3 bytes, byte0 = v0
__device__ __forceinline__ uint32_t pk4_e4m3(float v0, float v1, float v2, float v3){
    uint16_t h0, h1;
    asm("cvt.rn.satfinite.e4m3x2.f32 %0, %1, %2;" : "=h"(h0) : "f"(v1), "f"(v0));
    asm("cvt.rn.satfinite.e4m3x2.f32 %0, %1, %2;" : "=h"(h1) : "f"(v3), "f"(v2));
    return (uint32_t)h0 | ((uint32_t)h1 << 16);
}

#define CP16(dst, src) \
    asm volatile("cp.async.cg.shared.global [%0], [%1], 16;\n" :: "r"(dst), "l"(src))
#define CP_COMMIT()  asm volatile("cp.async.commit_group;\n" ::)
#define CP_WAIT1()   asm volatile("cp.async.wait_group 1;\n" ::)

#define LDSM4(r0,r1,r2,r3,addr) \
    asm volatile("ldmatrix.sync.aligned.m8n8.x4.shared.b16 {%0,%1,%2,%3}, [%4];" \
                 : "=r"(r0), "=r"(r1), "=r"(r2), "=r"(r3) : "r"(addr))
#define LDSM4T(r0,r1,r2,r3,addr) \
    asm volatile("ldmatrix.sync.aligned.m8n8.x4.trans.shared.b16 {%0,%1,%2,%3}, [%4];" \
                 : "=r"(r0), "=r"(r1), "=r"(r2), "=r"(r3) : "r"(addr))
#define MMA16816(c0,c1,c2,c3,a0,a1,a2,a3,b0,b1) \
    asm volatile( \
        "mma.sync.aligned.m16n8k16.row.col.f32.bf16.bf16.f32 " \
        "{%0,%1,%2,%3}, {%4,%5,%6,%7}, {%8,%9}, {%0,%1,%2,%3};\n" \
        : "+f"(c0), "+f"(c1), "+f"(c2), "+f"(c3) \
        : "r"(a0), "r"(a1), "r"(a2), "r"(a3), "r"(b0), "r"(b1))
#define MMAF8(c0,c1,c2,c3,a0,a1,a2,a3,b0,b1) \
    asm volatile( \
        "mma.sync.aligned.m16n8k32.row.col.f32.e4m3.e4m3.f32 " \
        "{%0,%1,%2,%3}, {%4,%5,%6,%7}, {%8,%9}, {%0,%1,%2,%3};\n" \
        : "+f"(c0), "+f"(c1), "+f"(c2), "+f"(c3) \
        : "r"(a0), "r"(a1), "r"(a2), "r"(a3), "r"(b0), "r"(b1))

// ---------------- merge kernels ----------------
// fused g1/g2/gf merge (one launch)
__global__ void merge_g_all(const float* __restrict__ g1, const float* __restrict__ g2,
                            const float* __restrict__ gf,
                            const float* __restrict__ d_g1, const float* __restrict__ d_g2,
                            const float* __restrict__ d_gf,
                            const float* __restrict__ lam,
                            float* __restrict__ o1, float* __restrict__ o2,
                            float* __restrict__ of){
    int i = blockIdx.x*blockDim.x + threadIdx.x;
    float l0 = lam[0], l1 = lam[1];
    if (i < L_*D_){
        o1[i] = g1[i] + l0*d_g1[i] + l1*d_g1[L_*D_ + i];
        o2[i] = g2[i] + l0*d_g2[i] + l1*d_g2[L_*D_ + i];
    }
    if (i < D_)
        of[i] = gf[i] + l0*d_gf[i] + l1*d_gf[D_ + i];
}
// emb merge: e4m3 out only (logits GEMM, scale 256)
__global__ void merge_emb_f8(const float* __restrict__ base,
                             const float* __restrict__ delta,
                             const float* __restrict__ lam,
                             uint32_t* __restrict__ outf8, size_t n){
    size_t n4 = n >> 2;
    float l0 = lam[0], l1 = lam[1];
    const float4* b4 = (const float4*)base;
    const float4* d0 = (const float4*)delta;
    const float4* d1 = (const float4*)(delta + n);
    for (size_t i = (size_t)blockIdx.x*blockDim.x + threadIdx.x; i < n4;
         i += (size_t)gridDim.x*blockDim.x){
        float4 b = b4[i], x0 = d0[i], x1 = d1[i];
        float r0 = b.x + l0*x0.x + l1*x1.x;
        float r1 = b.y + l0*x0.y + l1*x1.y;
        float r2 = b.z + l0*x0.z + l1*x1.z;
        float r3 = b.w + l0*x0.w + l1*x1.w;
        outf8[i] = pk4_e4m3(r0*256.f, r1*256.f, r2*256.f, r3*256.f);
    }
}
// transpose-merge -> bf16
__global__ void tmerge_kernel(const float* __restrict__ base,
                              const float* __restrict__ delta,
                              const float* __restrict__ lam,
                              bf16* __restrict__ out,
                              int K, int Nw, size_t tstride){
    __shared__ float tile[32][33];
    int z = blockIdx.z;
    size_t mo = (size_t)z*K*Nw;
    float l0 = lam[0], l1 = lam[1];
    int n0 = blockIdx.x*32, k0 = blockIdx.y*32;
    #pragma unroll
    for (int j = 0; j < 32; j += 8){
        int k = k0 + threadIdx.y + j;
        int nn = n0 + threadIdx.x;
        size_t idx = mo + (size_t)k*Nw + nn;
        tile[threadIdx.y + j][threadIdx.x] =
            base[idx] + l0*delta[idx] + l1*delta[tstride + idx];
    }
    __syncthreads();
    #pragma unroll
    for (int j = 0; j < 32; j += 8){
        int nn = n0 + threadIdx.y + j;
        int k = k0 + threadIdx.x;
        out[mo + (size_t)nn*K + k] = __float2bfloat16(tile[threadIdx.x][threadIdx.y + j]);
    }
}
// transpose-merge -> packed e4m3 (x scale)
__global__ void tmerge_f8(const float* __restrict__ base,
                          const float* __restrict__ delta,
                          const float* __restrict__ lam,
                          uint32_t* __restrict__ out,
                          int K, int Nw, size_t tstride, float scale){
    __shared__ float tile[32][33];
    int z = blockIdx.z;
    size_t mo = (size_t)z*K*Nw;
    float l0 = lam[0], l1 = lam[1];
    int n0 = blockIdx.x*32, k0 = blockIdx.y*32;
    #pragma unroll
    for (int j = 0; j < 32; j += 8){
        int k = k0 + threadIdx.y + j;
        int nn = n0 + threadIdx.x;
        size_t idx = mo + (size_t)k*Nw + nn;
        tile[threadIdx.y + j][threadIdx.x] =
            base[idx] + l0*delta[idx] + l1*delta[tstride + idx];
    }
    __syncthreads();
    int tid = threadIdx.y*32 + threadIdx.x;
    int nn_l = tid >> 3;
    int kg = tid & 7;
    int nn = n0 + nn_l;
    int kk = kg*4;
    float v0 = tile[kk][nn_l]   * scale;
    float v1 = tile[kk+1][nn_l] * scale;
    float v2 = tile[kk+2][nn_l] * scale;
    float v3 = tile[kk+3][nn_l] * scale;
    out[((mo + (size_t)nn*K + k0) >> 2) + kg] = pk4_e4m3(v0, v1, v2, v3);
}

// ---------------- gather with on-the-fly merge ----------------
__global__ void gather_merge(const int* __restrict__ ids,
                             const float* __restrict__ emb,
                             const float* __restrict__ demb,
                             const float* __restrict__ lam,
                             float* __restrict__ x){
    int t = blockIdx.x;
    int id = ids[t];
    float l0 = lam[0], l1 = lam[1];
    const float4* b  = (const float4*)(emb  + (size_t)id*D_);
    const float4* e0 = (const float4*)(demb + (size_t)id*D_);
    const float4* e1 = (const float4*)(demb + (size_t)V_*D_ + (size_t)id*D_);
    float4* dst = (float4*)(x + (size_t)t*D_);
    for (int d = threadIdx.x; d < D_/4; d += blockDim.x){
        float4 bb = b[d], x0 = e0[d], x1 = e1[d], r;
        r.x = bb.x + l0*x0.x + l1*x1.x;
        r.y = bb.y + l0*x0.y + l1*x1.y;
        r.z = bb.z + l0*x0.z + l1*x1.z;
        r.w = bb.w + l0*x0.w + l1*x1.w;
        dst[d] = r;
    }
}

// ---------------- layernorm ----------------
__global__ void ln_kernel(const float* __restrict__ x,
                          const float* __restrict__ g,
                          bf16* __restrict__ out){
    int t = blockIdx.x;
    int tid = threadIdx.x;
    const float* xr = x + (size_t)t*D_;
    float s = 0.f, ss = 0.f;
    for (int d = tid; d < D_; d += 256){ float v = xr[d]; s += v; ss = fmaf(v, v, ss); }
    float tots = block_reduce<false>(s);
    float totss = block_reduce<false>(ss);
    float mu = tots * (1.f/D_);
    float var = totss * (1.f/D_) - mu*mu;
    float inv = rsqrtf(var + 1e-5f);
    bf16* orow = out + (size_t)t*D_;
    for (int d = tid; d < D_; d += 256)
        orow[d] = __float2bfloat16((xr[d]-mu)*inv*g[d]);
}
// LN -> e4m3 packed, scale 4
__global__ void ln_f8_kernel(const float* __restrict__ x,
                             const float* __restrict__ g,
                             uint32_t* __restrict__ out){
    int t = blockIdx.x;
    int tid = threadIdx.x;
    const float* xr = x + (size_t)t*D_;
    float s = 0.f, ss = 0.f;
    for (int d = tid; d < D_; d += 256){ float v = xr[d]; s += v; ss = fmaf(v, v, ss); }
    float tots = block_reduce<false>(s);
    float totss = block_reduce<false>(ss);
    float mu = tots * (1.f/D_);
    float var = totss * (1.f/D_) - mu*mu;
    float inv = rsqrtf(var + 1e-5f);
    int d = tid*4;
    float v0 = (xr[d]-mu)*inv*g[d]     * 4.f;
    float v1 = (xr[d+1]-mu)*inv*g[d+1] * 4.f;
    float v2 = (xr[d+2]-mu)*inv*g[d+2] * 4.f;
    float v3 = (xr[d+3]-mu)*inv*g[d+3] * 4.f;
    out[(size_t)t*(D_/4) + tid] = pk4_e4m3(v0, v1, v2, v3);
}

// ================= bf16 GEMM (NT, 2-stage cp.async + ldmatrix) ============
#define PAD 40

template<int ACT, int RES, int OUTBF>
__global__ void __launch_bounds__(256) hgemm(int M, int N, int K,
                        const bf16* __restrict__ A,
                        const bf16* __restrict__ Bt,
                        const float* __restrict__ Res,
                        void* __restrict__ Cout){
    __shared__ __align__(16) bf16 As[2][128*PAD];
    __shared__ __align__(16) bf16 Bs[2][128*PAD];

    const int tid  = threadIdx.x;
    const int lane = tid & 31;
    const int warp = tid >> 5;
    const int g    = lane >> 2;
    const int t    = lane & 3;
    const int wm   = warp >> 1;
    const int wn   = warp & 1;
    const int row0 = blockIdx.x * 128;
    const int col0 = blockIdx.y * 128;

    float c[2][8][4];
    #pragma unroll
    for (int i=0;i<2;i++)
        #pragma unroll
        for (int j=0;j<8;j++)
            #pragma unroll
            for (int k=0;k<4;k++) c[i][j][k]=0.f;

    const int r1 = tid >> 2;
    const int c8 = (tid & 3) * 8;
    const bf16* Ag0 = A  + (size_t)(row0 + r1)*K + c8;
    const bf16* Ag1 = A  + (size_t)(row0 + r1 + 64)*K + c8;
    const bf16* Bg0 = Bt + (size_t)(col0 + r1)*K + c8;
    const bf16* Bg1 = Bt + (size_t)(col0 + r1 + 64)*K + c8;
    const uint32_t sa0 = sptr(&As[0][r1*PAD + c8]);
    const uint32_t sa1 = sptr(&As[0][(r1+64)*PAD + c8]);
    const uint32_t sb0 = sptr(&Bs[0][r1*PAD + c8]);
    const uint32_t sb1 = sptr(&Bs[0][(r1+64)*PAD + c8]);
    const uint32_t SS = 128*PAD*2;

    uint32_t aAddr[2];
    #pragma unroll
    for (int mt = 0; mt < 2; mt++)
        aAddr[mt] = sptr(&As[0][(wm*32 + mt*16 + (lane & 15))*PAD + (lane >> 4)*8]);
    uint32_t bAddr[4];
    #pragma unroll
    for (int bt = 0; bt < 4; bt++)
        bAddr[bt] = sptr(&Bs[0][(wn*64 + bt*16 + ((lane>>4)&1)*8 + (lane&7))*PAD
                                + ((lane>>3)&1)*8]);

    {
        CP16(sa0, Ag0); CP16(sa1, Ag1);
        CP16(sb0, Bg0); CP16(sb1, Bg1);
        CP_COMMIT();
    }

    const int KT = K >> 5;
    int s = 0;
    for (int kt = 0; kt < KT; kt++){
        if (kt + 1 < KT){
            const int ko = (kt + 1) << 5;
            const uint32_t so = (s ^ 1) * SS;
            CP16(sa0 + so, Ag0 + ko); CP16(sa1 + so, Ag1 + ko);
            CP16(sb0 + so, Bg0 + ko); CP16(sb1 + so, Bg1 + ko);
        }
        CP_COMMIT();
        CP_WAIT1();
        __syncthreads();

        const uint32_t sb = s * SS;
        #pragma unroll
        for (int ks = 0; ks < 2; ks++){
            const uint32_t kb = sb + ks*32;
            uint32_t a[2][4];
            #pragma unroll
            for (int mt = 0; mt < 2; mt++)
                LDSM4(a[mt][0], a[mt][1], a[mt][2], a[mt][3], aAddr[mt] + kb);
            uint32_t bb[4][4];
            #pragma unroll
            for (int bt = 0; bt < 4; bt++)
                LDSM4(bb[bt][0], bb[bt][1], bb[bt][2], bb[bt][3], bAddr[bt] + kb);
            #pragma unroll
            for (int mt = 0; mt < 2; mt++)
                #pragma unroll
                for (int nt = 0; nt < 8; nt++){
                    const int bt = nt >> 1, su = (nt & 1) * 2;
                    MMA16816(c[mt][nt][0], c[mt][nt][1], c[mt][nt][2], c[mt][nt][3],
                             a[mt][0], a[mt][1], a[mt][2], a[mt][3],
                             bb[bt][su], bb[bt][su+1]);
                }
        }
        __syncthreads();
        s ^= 1;
    }

    float* Cf = (float*)Cout;
    bf16*  Ch = (bf16*)Cout;
    #pragma unroll
    for (int mt = 0; mt < 2; mt++){
        int r0 = row0 + wm*32 + mt*16 + g;
        #pragma unroll
        for (int nt = 0; nt < 8; nt++){
            int cc = col0 + wn*64 + nt*8 + 2*t;
            float v0 = c[mt][nt][0], v1 = c[mt][nt][1];
            float v2 = c[mt][nt][2], v3 = c[mt][nt][3];
            if (RES){
                v0 += Res[(size_t)r0*N + cc];
                v1 += Res[(size_t)r0*N + cc + 1];
                v2 += Res[(size_t)(r0+8)*N + cc];
                v3 += Res[(size_t)(r0+8)*N + cc + 1];
            }
            if (ACT){
                v0 = gelu_f(v0); v1 = gelu_f(v1);
                v2 = gelu_f(v2); v3 = gelu_f(v3);
            }
            if (OUTBF){
                *(__nv_bfloat162*)&Ch[(size_t)r0*N + cc]     = __floats2bfloat162_rn(v0, v1);
                *(__nv_bfloat162*)&Ch[(size_t)(r0+8)*N + cc] = __floats2bfloat162_rn(v2, v3);
            } else {
                Cf[(size_t)r0*N + cc]         = v0;
                Cf[(size_t)r0*N + cc + 1]     = v1;
                Cf[(size_t)(r0+8)*N + cc]     = v2;
                Cf[(size_t)(r0+8)*N + cc + 1] = v3;
            }
        }
    }
}

// ================= FP8 GEMM (2-stage, generic epilogue) ===================
// OUT: 0 = fp32 (+Res), 2 = packed e4m3 (x osc)
template<int ACT, int RES, int OUT>
__global__ void __launch_bounds__(256) f8gemm(int K16, int N,
                        const bf16* __restrict__ A,
                        const bf16* __restrict__ Bt,
                        const float* __restrict__ Res,
                        void* __restrict__ Cout,
                        float dsc, float osc){
    __shared__ __align__(16) bf16 As[2][128*PAD];
    __shared__ __align__(16) bf16 Bs[2][128*PAD];

    const int tid  = threadIdx.x;
    const int lane = tid & 31;
    const int warp = tid >> 5;
    const int g    = lane >> 2;
    const int t    = lane & 3;
    const int wm   = warp >> 1;
    const int wn   = warp & 1;
    const int row0 = blockIdx.x * 128;
    const int col0 = blockIdx.y * 128;
    const int K = K16;

    float c[2][8][4];
    #pragma unroll
    for (int i=0;i<2;i++)
        #pragma unroll
        for (int j=0;j<8;j++)
            #pragma unroll
            for (int k=0;k<4;k++) c[i][j][k]=0.f;

    const int r1 = tid >> 2;
    const int c8 = (tid & 3) * 8;
    const bf16* Ag0 = A  + (size_t)(row0 + r1)*K + c8;
    const bf16* Ag1 = A  + (size_t)(row0 + r1 + 64)*K + c8;
    const bf16* Bg0 = Bt + (size_t)(col0 + r1)*K + c8;
    const bf16* Bg1 = Bt + (size_t)(col0 + r1 + 64)*K + c8;
    const uint32_t sa0 = sptr(&As[0][r1*PAD + c8]);
    const uint32_t sa1 = sptr(&As[0][(r1+64)*PAD + c8]);
    const uint32_t sb0 = sptr(&Bs[0][r1*PAD + c8]);
    const uint32_t sb1 = sptr(&Bs[0][(r1+64)*PAD + c8]);
    const uint32_t SS = 128*PAD*2;

    uint32_t aAddr[2];
    #pragma unroll
    for (int mt = 0; mt < 2; mt++)
        aAddr[mt] = sptr(&As[0][(wm*32 + mt*16 + (lane & 15))*PAD + (lane >> 4)*8]);
    uint32_t bAddr[4];
    #pragma unroll
    for (int bt = 0; bt < 4; bt++)
        bAddr[bt] = sptr(&Bs[0][(wn*64 + bt*16 + ((lane>>4)&1)*8 + (lane&7))*PAD
                                + ((lane>>3)&1)*8]);

    {
        CP16(sa0, Ag0); CP16(sa1, Ag1);
        CP16(sb0, Bg0); CP16(sb1, Bg1);
        CP_COMMIT();
    }

    const int KT = K >> 5;
    int s = 0;
    for (int kt = 0; kt < KT; kt++){
        if (kt + 1 < KT){
            const int ko = (kt + 1) << 5;
            const uint32_t so = (s ^ 1) * SS;
            CP16(sa0 + so, Ag0 + ko); CP16(sa1 + so, Ag1 + ko);
            CP16(sb0 + so, Bg0 + ko); CP16(sb1 + so, Bg1 + ko);
        }
        CP_COMMIT();
        CP_WAIT1();
        __syncthreads();

        const uint32_t sb = s * SS;
        #pragma unroll
        for (int ks = 0; ks < 2; ks++){
            const uint32_t kb = sb + ks*32;
            uint32_t a[2][4];
            #pragma unroll
            for (int mt = 0; mt < 2; mt++)
                LDSM4(a[mt][0], a[mt][1], a[mt][2], a[mt][3], aAddr[mt] + kb);
            uint32_t bb[4][4];
            #pragma unroll
            for (int bt = 0; bt < 4; bt++)
                LDSM4(bb[bt][0], bb[bt][1], bb[bt][2], bb[bt][3], bAddr[bt] + kb);
            #pragma unroll
            for (int mt = 0; mt < 2; mt++)
                #pragma unroll
                for (int nt = 0; nt < 8; nt++){
                    const int bt = nt >> 1, su = (nt & 1) * 2;
                    MMAF8(c[mt][nt][0], c[mt][nt][1], c[mt][nt][2], c[mt][nt][3],
                          a[mt][0], a[mt][1], a[mt][2], a[mt][3],
                          bb[bt][su], bb[bt][su+1]);
                }
        }
        __syncthreads();
        s ^= 1;
    }

    float* Cf = (float*)Cout;
    uint32_t* C8 = (uint32_t*)Cout;
    #pragma unroll
    for (int mt = 0; mt < 2; mt++){
        int r0 = row0 + wm*32 + mt*16 + g;
        #pragma unroll
        for (int nt = 0; nt < 8; nt++){
            int cc = col0 + wn*64 + nt*8 + 2*t;
            float v0 = c[mt][nt][0]*dsc, v1 = c[mt][nt][1]*dsc;
            float v2 = c[mt][nt][2]*dsc, v3 = c[mt][nt][3]*dsc;
            if (RES){
                v0 += Res[(size_t)r0*N + cc];
                v1 += Res[(size_t)r0*N + cc + 1];
                v2 += Res[(size_t)(r0+8)*N + cc];
                v3 += Res[(size_t)(r0+8)*N + cc + 1];
            }
            if (ACT){
                v0 = gelu_f(v0); v1 = gelu_f(v1);
                v2 = gelu_f(v2); v3 = gelu_f(v3);
            }
            if (OUT == 2){
                v0 *= osc; v1 *= osc; v2 *= osc; v3 *= osc;
                float u0 = __shfl_xor_sync(0xffffffffu, v0, 1);
                float u1 = __shfl_xor_sync(0xffffffffu, v1, 1);
                float u2 = __shfl_xor_sync(0xffffffffu, v2, 1);
                float u3 = __shfl_xor_sync(0xffffffffu, v3, 1);
                if ((t & 1) == 0){
                    size_t i0 = ((size_t)r0*N + cc) >> 2;
                    size_t i1 = ((size_t)(r0+8)*N + cc) >> 2;
                    C8[i0] = pk4_e4m3(v0, v1, u0, u1);
                    C8[i1] = pk4_e4m3(v2, v3, u2, u3);
                }
            } else {
                Cf[(size_t)r0*N + cc]         = v0;
                Cf[(size_t)r0*N + cc + 1]     = v1;
                Cf[(size_t)(r0+8)*N + cc]     = v2;
                Cf[(size_t)(r0+8)*N + cc + 1] = v3;
            }
        }
    }
}

// ============ FP8 logits GEMM (2-stage) with fused logsumexp ==============
__global__ void __launch_bounds__(256) f8gemm_lse(int K16,
                        const bf16* __restrict__ A,
                        const bf16* __restrict__ Bt,
                        const int* __restrict__ labels,
                        float2* __restrict__ part,
                        float* __restrict__ tgtlog){
    __shared__ __align__(16) bf16 As[2][128*PAD];
    __shared__ __align__(16) bf16 Bs[2][128*PAD];
    __shared__ float2 red[2][128];
    __shared__ float  tgv[2][128];
    __shared__ float  tgf[2][128];

    const int tid  = threadIdx.x;
    const int lane = tid & 31;
    const int warp = tid >> 5;
    const int g    = lane >> 2;
    const int t    = lane & 3;
    const int wm   = warp >> 1;
    const int wn   = warp & 1;
    const int row0 = blockIdx.x * 128;
    const int col0 = blockIdx.y * 128;
    const int K = K16;

    float c[2][8][4];
    #pragma unroll
    for (int i=0;i<2;i++)
        #pragma unroll
        for (int j=0;j<8;j++)
            #pragma unroll
            for (int k=0;k<4;k++) c[i][j][k]=0.f;

    const int r1 = tid >> 2;
    const int c8 = (tid & 3) * 8;
    const bf16* Ag0 = A  + (size_t)(row0 + r1)*K + c8;
    const bf16* Ag1 = A  + (size_t)(row0 + r1 + 64)*K + c8;
    const bf16* Bg0 = Bt + (size_t)(col0 + r1)*K + c8;
    const bf16* Bg1 = Bt + (size_t)(col0 + r1 + 64)*K + c8;
    const uint32_t sa0 = sptr(&As[0][r1*PAD + c8]);
    const uint32_t sa1 = sptr(&As[0][(r1+64)*PAD + c8]);
    const uint32_t sb0 = sptr(&Bs[0][r1*PAD + c8]);
    const uint32_t sb1 = sptr(&Bs[0][(r1+64)*PAD + c8]);
    const uint32_t SS = 128*PAD*2;

    uint32_t aAddr[2];
    #pragma unroll
    for (int mt = 0; mt < 2; mt++)
        aAddr[mt] = sptr(&As[0][(wm*32 + mt*16 + (lane & 15))*PAD + (lane >> 4)*8]);
    uint32_t bAddr[4];
    #pragma unroll
    for (int bt = 0; bt < 4; bt++)
        bAddr[bt] = sptr(&Bs[0][(wn*64 + bt*16 + ((lane>>4)&1)*8 + (lane&7))*PAD
                                + ((lane>>3)&1)*8]);

    {
        CP16(sa0, Ag0); CP16(sa1, Ag1);
        CP16(sb0, Bg0); CP16(sb1, Bg1);
        CP_COMMIT();
    }

    const int KT = K >> 5;
    int s = 0;
    for (int kt = 0; kt < KT; kt++){
        if (kt + 1 < KT){
            const int ko = (kt + 1) << 5;
            const uint32_t so = (s ^ 1) * SS;
            CP16(sa0 + so, Ag0 + ko); CP16(sa1 + so, Ag1 + ko);
            CP16(sb0 + so, Bg0 + ko); CP16(sb1 + so, Bg1 + ko);
        }
        CP_COMMIT();
        CP_WAIT1();
        __syncthreads();

        const uint32_t sb = s * SS;
        #pragma unroll
        for (int ks = 0; ks < 2; ks++){
            const uint32_t kb = sb + ks*32;
            uint32_t a[2][4];
            #pragma unroll
            for (int mt = 0; mt < 2; mt++)
                LDSM4(a[mt][0], a[mt][1], a[mt][2], a[mt][3], aAddr[mt] + kb);
            uint32_t bb[4][4];
            #pragma unroll
            for (int bt = 0; bt < 4; bt++)
                LDSM4(bb[bt][0], bb[bt][1], bb[bt][2], bb[bt][3], bAddr[bt] + kb);
            #pragma unroll
            for (int mt = 0; mt < 2; mt++)
                #pragma unroll
                for (int nt = 0; nt < 8; nt++){
                    const int bt = nt >> 1, su = (nt & 1) * 2;
                    MMAF8(c[mt][nt][0], c[mt][nt][1], c[mt][nt][2], c[mt][nt][3],
                          a[mt][0], a[mt][1], a[mt][2], a[mt][3],
                          bb[bt][su], bb[bt][su+1]);
                }
        }
        __syncthreads();
        s ^= 1;
    }

    const float scale = 1.f/1024.f;
    #pragma unroll
    for (int mt = 0; mt < 2; mt++){
        #pragma unroll
        for (int half = 0; half < 2; half++){
            const int rowi = wm*32 + mt*16 + half*8 + g;
            const int token = row0 + rowi;
            const int ss2 = token & (S_-1);
            const int tgt = (ss2 == S_-1) ? -1
                          : labels[(token >> 10)*S_ + ss2 + 1];
            float rm = -1e30f;
            float v[16];
            #pragma unroll
            for (int nt = 0; nt < 8; nt++){
                v[2*nt]   = c[mt][nt][2*half]   * scale;
                v[2*nt+1] = c[mt][nt][2*half+1] * scale;
                rm = fmaxf(rm, fmaxf(v[2*nt], v[2*nt+1]));
            }
            float rs = 0.f, tv = 0.f, tf = 0.f;
            #pragma unroll
            for (int nt = 0; nt < 8; nt++){
                rs += __expf(v[2*nt] - rm) + __expf(v[2*nt+1] - rm);
                int col = col0 + wn*64 + nt*8 + 2*t;
                if (col   == tgt){ tv = v[2*nt];   tf = 1.f; }
                if (col+1 == tgt){ tv = v[2*nt+1]; tf = 1.f; }
            }
            #pragma unroll
            for (int o = 1; o <= 2; o <<= 1){
                float om = __shfl_xor_sync(0xffffffffu, rm, o);
                float os = __shfl_xor_sync(0xffffffffu, rs, o);
                float nm = fmaxf(rm, om);
                rs = rs*__expf(rm - nm) + os*__expf(om - nm);
                rm = nm;
                tv += __shfl_xor_sync(0xffffffffu, tv, o);
                tf += __shfl_xor_sync(0xffffffffu, tf, o);
            }
            if (t == 0){
                red[wn][rowi] = make_float2(rm, rs);
                tgv[wn][rowi] = tv;
                tgf[wn][rowi] = tf;
            }
        }
    }
    __syncthreads();
    if (tid < 128){
        float2 p0 = red[0][tid], p1 = red[1][tid];
        float m = fmaxf(p0.x, p1.x);
        float sm = p0.y*__expf(p0.x - m) + p1.y*__expf(p1.x - m);
        int token = row0 + tid;
        part[(size_t)token*256 + blockIdx.y] = make_float2(m, sm);
        if (tgf[0][tid] + tgf[1][tid] > 0.5f)
            tgtlog[token] = tgv[0][tid] + tgv[1][tid];
    }
}

// ================= fused flash attention ==================================
// qt reversed (longest CTAs scheduled first -> better tail packing)
#define QPAD 72

__global__ void __launch_bounds__(256) flash_attn(const bf16* __restrict__ qkv,
                                                  bf16* __restrict__ out){
    __shared__ __align__(16) bf16 Qs[128*QPAD];
    __shared__ __align__(16) bf16 Ks[2][64*QPAD];
    __shared__ __align__(16) bf16 Vs[2][64*QPAD];

    const int tid  = threadIdx.x;
    const int lane = tid & 31;
    const int warp = tid >> 5;
    const int g    = lane >> 2;
    const int t    = lane & 3;
    const int qt   = gridDim.x - 1 - blockIdx.x;   // longest-first scheduling
    const int bh   = blockIdx.y;
    const int b    = bh >> 4, h = bh & 15;
    const int q0   = qt * 128;

    const size_t tok0 = (size_t)b * S_;
    const bf16* Qg = qkv + (tok0 + q0)*(3*D_) + h*HD_;
    const bf16* Kg = qkv + tok0*(3*D_) + D_   + h*HD_;
    const bf16* Vg = qkv + tok0*(3*D_) + 2*D_ + h*HD_;

    {
        #pragma unroll
        for (int j = 0; j < 4; j++){
            int ch = tid + j*256;
            int r = ch >> 3, c = (ch & 7)*8;
            CP16(sptr(&Qs[r*QPAD + c]), Qg + (size_t)r*(3*D_) + c);
        }
        #pragma unroll
        for (int j = 0; j < 2; j++){
            int ch = tid + j*256;
            int r = ch >> 3, c = (ch & 7)*8;
            CP16(sptr(&Ks[0][r*QPAD + c]), Kg + (size_t)r*(3*D_) + c);
            CP16(sptr(&Vs[0][r*QPAD + c]), Vg + (size_t)r*(3*D_) + c);
        }
        CP_COMMIT();
    }

    float m0 = -1e30f, m1 = -1e30f, l0 = 0.f, l1 = 0.f;
    float o[8][4];
    #pragma unroll
    for (int i=0;i<8;i++){ o[i][0]=0.f; o[i][1]=0.f; o[i][2]=0.f; o[i][3]=0.f; }

    const uint32_t aQ = sptr(&Qs[(warp*16 + (lane & 15))*QPAD + (lane >> 4)*8]);
    uint32_t kA[4], vA[4];
    #pragma unroll
    for (int bt = 0; bt < 4; bt++)
        kA[bt] = sptr(&Ks[0][(bt*16 + ((lane>>4)&1)*8 + (lane&7))*QPAD
                             + ((lane>>3)&1)*8]);
    #pragma unroll
    for (int dt = 0; dt < 4; dt++)
        vA[dt] = sptr(&Vs[0][(((lane>>3)&1)*8 + (lane&7))*QPAD
                             + dt*16 + ((lane>>4)&1)*8]);
    const uint32_t KVS = 64*QPAD*2;

    const int nkt = 2*qt + 2;
    int s = 0;
    for (int kt = 0; kt < nkt; kt++){
        if (kt + 1 < nkt){
            const bf16* Kg2 = Kg + (size_t)(kt+1)*64*(3*D_);
            const bf16* Vg2 = Vg + (size_t)(kt+1)*64*(3*D_);
            bf16* ksm = &Ks[s^1][0];
            bf16* vsm = &Vs[s^1][0];
            #pragma unroll
            for (int j = 0; j < 2; j++){
                int ch = tid + j*256;
                int r = ch >> 3, c = (ch & 7)*8;
                CP16(sptr(ksm + r*QPAD + c), Kg2 + (size_t)r*(3*D_) + c);
                CP16(sptr(vsm + r*QPAD + c), Vg2 + (size_t)r*(3*D_) + c);
            }
        }
        CP_COMMIT();
        CP_WAIT1();
        __syncthreads();

        const uint32_t so = s * KVS;

        float sc[8][4];
        #pragma unroll
        for (int i=0;i<8;i++){ sc[i][0]=0.f; sc[i][1]=0.f; sc[i][2]=0.f; sc[i][3]=0.f; }
        #pragma unroll
        for (int kk = 0; kk < 4; kk++){
            uint32_t a0,a1,a2,a3;
            LDSM4(a0,a1,a2,a3, aQ + kk*32);
            uint32_t bb[4][4];
            #pragma unroll
            for (int bt = 0; bt < 4; bt++)
                LDSM4(bb[bt][0],bb[bt][1],bb[bt][2],bb[bt][3], kA[bt] + so + kk*32);
            #pragma unroll
            for (int nt = 0; nt < 8; nt++){
                const int bt = nt >> 1, su = (nt & 1)*2;
                MMA16816(sc[nt][0],sc[nt][1],sc[nt][2],sc[nt][3],
                         a0,a1,a2,a3, bb[bt][su], bb[bt][su+1]);
            }
        }

        const int qrow0 = q0 + warp*16 + g;
        const int qrow1 = qrow0 + 8;
        const bool masked = (kt >= 2*qt);
        #pragma unroll
        for (int nt = 0; nt < 8; nt++){
            int col = kt*64 + nt*8 + 2*t;
            #pragma unroll
            for (int u = 0; u < 4; u++) sc[nt][u] *= 0.125f;
            if (masked){
                if (col   > qrow0) sc[nt][0] = -1e30f;
                if (col+1 > qrow0) sc[nt][1] = -1e30f;
                if (col   > qrow1) sc[nt][2] = -1e30f;
                if (col+1 > qrow1) sc[nt][3] = -1e30f;
            }
        }

        float tm0 = -1e30f, tm1 = -1e30f;
        #pragma unroll
        for (int nt = 0; nt < 8; nt++){
            tm0 = fmaxf(tm0, fmaxf(sc[nt][0], sc[nt][1]));
            tm1 = fmaxf(tm1, fmaxf(sc[nt][2], sc[nt][3]));
        }
        tm0 = fmaxf(tm0, __shfl_xor_sync(0xffffffffu, tm0, 1));
        tm0 = fmaxf(tm0, __shfl_xor_sync(0xffffffffu, tm0, 2));
        tm1 = fmaxf(tm1, __shfl_xor_sync(0xffffffffu, tm1, 1));
        tm1 = fmaxf(tm1, __shfl_xor_sync(0xffffffffu, tm1, 2));
        float nm0 = fmaxf(m0, tm0), nm1 = fmaxf(m1, tm1);
        float al0 = __expf(m0 - nm0), al1 = __expf(m1 - nm1);
        m0 = nm0; m1 = nm1;
        float ps0 = 0.f, ps1 = 0.f;
        #pragma unroll
        for (int nt = 0; nt < 8; nt++){
            sc[nt][0] = __expf(sc[nt][0] - nm0);
            sc[nt][1] = __expf(sc[nt][1] - nm0);
            sc[nt][2] = __expf(sc[nt][2] - nm1);
            sc[nt][3] = __expf(sc[nt][3] - nm1);
            ps0 += sc[nt][0] + sc[nt][1];
            ps1 += sc[nt][2] + sc[nt][3];
        }
        l0 = l0*al0 + ps0;
        l1 = l1*al1 + ps1;
        #pragma unroll
        for (int dt = 0; dt < 8; dt++){
            o[dt][0] *= al0; o[dt][1] *= al0;
            o[dt][2] *= al1; o[dt][3] *= al1;
        }

        #pragma unroll
        for (int kk = 0; kk < 4; kk++){
            uint32_t a0 = pk2(sc[2*kk][0],   sc[2*kk][1]);
            uint32_t a1 = pk2(sc[2*kk][2],   sc[2*kk][3]);
            uint32_t a2 = pk2(sc[2*kk+1][0], sc[2*kk+1][1]);
            uint32_t a3 = pk2(sc[2*kk+1][2], sc[2*kk+1][3]);
            uint32_t vv[4][4];
            #pragma unroll
            for (int dt = 0; dt < 4; dt++)
                LDSM4T(vv[dt][0],vv[dt][1],vv[dt][2],vv[dt][3],
                       vA[dt] + so + kk*16*QPAD*2);
            #pragma unroll
            for (int nt = 0; nt < 8; nt++){
                const int dt = nt >> 1, su = (nt & 1)*2;
                MMA16816(o[nt][0],o[nt][1],o[nt][2],o[nt][3],
                         a0,a1,a2,a3, vv[dt][su], vv[dt][su+1]);
            }
        }
        __syncthreads();
        s ^= 1;
    }

    l0 += __shfl_xor_sync(0xffffffffu, l0, 1);
    l0 += __shfl_xor_sync(0xffffffffu, l0, 2);
    l1 += __shfl_xor_sync(0xffffffffu, l1, 1);
    l1 += __shfl_xor_sync(0xffffffffu, l1, 2);
    float r0 = 1.f/l0, r1 = 1.f/l1;
    const int row0 = q0 + warp*16 + g;
    bf16* O0 = out + (tok0 + row0)*D_ + h*HD_;
    bf16* O1 = out + (tok0 + row0 + 8)*D_ + h*HD_;
    #pragma unroll
    for (int dt = 0; dt < 8; dt++){
        int cc = dt*8 + 2*t;
        *(__nv_bfloat162*)&O0[cc] = __floats2bfloat162_rn(o[dt][0]*r0, o[dt][1]*r0);
        *(__nv_bfloat162*)&O1[cc] = __floats2bfloat162_rn(o[dt][2]*r1, o[dt][3]*r1);
    }
}

// ---------------- NLL final ----------------
__global__ void nll_final(const float2* __restrict__ part,
                          const float* __restrict__ tgtlog,
                          float* __restrict__ nll){
    int t = blockIdx.x, tid = threadIdx.x;
    int ss = t & (S_-1);
    if (ss == S_-1){ if (tid == 0) nll[t] = 0.f; return; }
    float2 p = (tid < V_/128) ? part[(size_t)t*256 + tid]
                              : make_float2(-1e30f, 0.f);
    float M = block_reduce<true>(p.x);
    float S = block_reduce<false>(p.y * __expf(p.x - M));
    if (tid == 0) nll[t] = logf(S) + M - tgtlog[t];
}

// ---------------- final mean ----------------
__global__ void final_reduce(const float* __restrict__ nll, float* __restrict__ out){
    float s = 0.f;
    for (int t = threadIdx.x; t < N_; t += 256)
        if ((t & (S_-1)) != S_-1) s += nll[t];
    s = block_reduce<false>(s);
    if (threadIdx.x == 0) out[0] = s * (1.f/(B_*(S_-1)));
}

// ---------------- side stream (created at static init) ----------------
struct SideStream {
    cudaStream_t s2;
    cudaEvent_t fork, join, join2;
    SideStream(){
        cudaStreamCreateWithFlags(&s2, cudaStreamNonBlocking);
        cudaEventCreateWithFlags(&fork,  cudaEventDisableTiming);
        cudaEventCreateWithFlags(&join,  cudaEventDisableTiming);
        cudaEventCreateWithFlags(&join2, cudaEventDisableTiming);
    }
};
static SideStream g_ss;

// ---------------- host launch ----------------
static inline int mgrid(size_t n){
    size_t n4 = n >> 2;
    return (int)((n4 + 255) / 256);
}

extern "C" void kernel_launch(void* const* d_in, const int* in_sizes, int n_in,
                              void* d_out, int out_size){
    const int*   ids    = (const int*)  d_in[0];
    const int*   labels = (const int*)  d_in[1];
    const float* lam    = (const float*)d_in[2];
    const float* emb    = (const float*)d_in[3];
    const float* Wqkv   = (const float*)d_in[4];
    const float* Wo     = (const float*)d_in[5];
    const float* W1     = (const float*)d_in[6];
    const float* W2     = (const float*)d_in[7];
    const float* g1     = (const float*)d_in[8];
    const float* g2     = (const float*)d_in[9];
    const float* gf     = (const float*)d_in[10];
    const float* d_emb  = (const float*)d_in[11];
    const float* d_Wqkv = (const float*)d_in[12];
    const float* d_Wo   = (const float*)d_in[13];
    const float* d_W1   = (const float*)d_in[14];
    const float* d_W2   = (const float*)d_in[15];
    const float* d_g1   = (const float*)d_in[16];
    const float* d_g2   = (const float*)d_in[17];
    const float* d_gf   = (const float*)d_in[18];

    float *p_g1, *p_g2, *p_gf, *p_x, *p_tgt, *p_nll;
    bf16  *p_WqkvT, *p_WoT, *p_a, *p_o, *p_qkvh;
    uint32_t *p_embf8, *p_af8, *p_W18, *p_W28, *p_ff8;
    float2 *p_part;
    cudaGetSymbolAddress((void**)&p_embf8,  g_embf8);
    cudaGetSymbolAddress((void**)&p_WqkvT,  g_WqkvT);
    cudaGetSymbolAddress((void**)&p_WoT,    g_WoT);
    cudaGetSymbolAddress((void**)&p_W18,    g_W18);
    cudaGetSymbolAddress((void**)&p_W28,    g_W28);
    cudaGetSymbolAddress((void**)&p_g1,     g_g1);
    cudaGetSymbolAddress((void**)&p_g2,     g_g2);
    cudaGetSymbolAddress((void**)&p_gf,     g_gfm);
    cudaGetSymbolAddress((void**)&p_x,      g_x);
    cudaGetSymbolAddress((void**)&p_a,      g_a);
    cudaGetSymbolAddress((void**)&p_af8,    g_af8);
    cudaGetSymbolAddress((void**)&p_qkvh,   g_qkvh);
    cudaGetSymbolAddress((void**)&p_o,      g_o);
    cudaGetSymbolAddress((void**)&p_ff8,    g_ff8);
    cudaGetSymbolAddress((void**)&p_part,   g_part);
    cudaGetSymbolAddress((void**)&p_tgt,    g_tgt);
    cudaGetSymbolAddress((void**)&p_nll,    g_nll);

    size_t n;
    dim3 t328(32, 8);

    // ---- fork: side stream runs BW-bound merges needed late ----
    cudaEventRecord(g_ss.fork, 0);
    cudaStreamWaitEvent(g_ss.s2, g_ss.fork, 0);
    tmerge_kernel<<<dim3(D_/32, D_/32, L_), t328, 0, g_ss.s2>>>(
        Wo, d_Wo, lam, p_WoT, D_, D_, (size_t)L_*D_*D_);
    tmerge_f8<<<dim3(DFF_/32, D_/32, L_), t328, 0, g_ss.s2>>>(
        W1, d_W1, lam, p_W18, D_, DFF_, (size_t)L_*D_*DFF_, 256.f);
    tmerge_f8<<<dim3(D_/32, DFF_/32, L_), t328, 0, g_ss.s2>>>(
        W2, d_W2, lam, p_W28, DFF_, D_, (size_t)L_*DFF_*D_, 256.f);
    cudaEventRecord(g_ss.join, g_ss.s2);
    n = (size_t)V_*D_;
    merge_emb_f8<<<mgrid(n),256,0,g_ss.s2>>>(emb, d_emb, lam, p_embf8, n);
    cudaEventRecord(g_ss.join2, g_ss.s2);

    // ---- main stream: what layer 0's prefix needs ----
    gather_merge<<<N_, 256>>>(ids, emb, d_emb, lam, p_x);
    merge_g_all<<<(L_*D_ + 255)/256, 256>>>(g1, g2, gf, d_g1, d_g2, d_gf,
                                            lam, p_g1, p_g2, p_gf);
    tmerge_kernel<<<dim3(3*D_/32, D_/32, L_), t328>>>(Wqkv, d_Wqkv, lam, p_WqkvT,
                     D_, 3*D_, (size_t)L_*D_*3*D_);

    for (int l = 0; l < L_; l++){
        // attn (bf16 path)
        ln_kernel<<<N_,256>>>(p_x, p_g1 + l*D_, p_a);
        hgemm<0,0,1><<<dim3(N_/128, 3*D_/128), 256>>>(N_, 3*D_, D_, p_a,
                         p_WqkvT + (size_t)l*3*D_*D_, nullptr, p_qkvh);
        flash_attn<<<dim3(S_/128, B_*H_), 256>>>(p_qkvh, p_o);
        if (l == 0) cudaStreamWaitEvent(0, g_ss.join, 0);   // W merges ready
        hgemm<0,1,0><<<dim3(N_/128, D_/128), 256>>>(N_, D_, D_, p_o,
                         p_WoT + (size_t)l*D_*D_, p_x, p_x);
        // ffn (fp8 path)
        ln_f8_kernel<<<N_,256>>>(p_x, p_g2 + l*D_, p_af8);
        f8gemm<1,0,2><<<dim3(N_/128, DFF_/128), 256>>>(D_/2, DFF_,
            (const bf16*)p_af8, (const bf16*)(p_W18 + (size_t)l*DFF_*D_/4),
            nullptr, p_ff8, 1.f/1024.f, 16.f);
        f8gemm<0,1,0><<<dim3(N_/128, D_/128), 256>>>(DFF_/2, D_,
            (const bf16*)p_ff8, (const bf16*)(p_W28 + (size_t)l*D_*DFF_/4),
            p_x, p_x, 1.f/4096.f, 1.f);
    }

    // ---- head: fp8 logits GEMM with fused logsumexp ----
    ln_f8_kernel<<<N_,256>>>(p_x, p_gf, p_af8);
    cudaStreamWaitEvent(0, g_ss.join2, 0);                  // emb merge ready
    f8gemm_lse<<<dim3(N_/128, V_/128), 256>>>(D_/2,
        (const bf16*)p_af8, (const bf16*)p_embf8, labels, p_part, p_tgt);
    nll_final<<<N_,256>>>(p_part, p_tgt, p_nll);
    final_reduce<<<1,256>>>(p_nll, (float*)d_out);
}

// round 15
// speedup vs baseline: 1.0199x; 1.0178x over previous
#include <cuda_runtime.h>
#include <cuda_bf16.h>
#include <math.h>
#include <stddef.h>
#include <stdint.h>

#define L_   2
#define D_   1024
#define H_   16
#define HD_  64
#define DFF_ 4096
#define V_   32000
#define B_   2
#define S_   1024
#define N_   (B_*S_)   // 2048 tokens

typedef __nv_bfloat16 bf16;

// ---------------- device scratch (static, no allocations) ----------------
__device__ uint32_t g_embf8[(size_t)V_*D_/4];    // e4m3 x4 packed, scale 256
__device__ bf16  g_WqkvT[(size_t)L_*3*D_*D_];    // bf16 [l][3D][D]
__device__ bf16  g_WoT [(size_t)L_*D_*D_];       // bf16 [l][D][D]
__device__ uint32_t g_W18[(size_t)L_*DFF_*D_/4]; // e4m3 [l][DFF][D], scale 256
__device__ uint32_t g_W28[(size_t)L_*D_*DFF_/4]; // e4m3 [l][D][DFF], scale 256
__device__ float g_g1  [L_*D_];
__device__ float g_g2  [L_*D_];
__device__ float g_gfm [D_];
__device__ float g_x   [(size_t)N_*D_];
__device__ bf16  g_a   [(size_t)N_*D_];          // LN1 output (bf16)
__device__ uint32_t g_af8[(size_t)N_*D_/4];      // LN2/final-LN e4m3 x4, scale 4
__device__ bf16  g_qkvh[(size_t)N_*3*D_];
__device__ bf16  g_o   [(size_t)N_*D_];
__device__ uint32_t g_ff8[(size_t)N_*DFF_/4];    // GELU out e4m3, scale 16
__device__ float2 g_part[(size_t)N_*256];        // [token][nblock] lse partials
__device__ float g_tgt [N_];
__device__ float g_nll [N_];

// ---------------- helpers ----------------
__device__ __forceinline__ float warp_sum(float v){
    #pragma unroll
    for (int o=16;o;o>>=1) v += __shfl_down_sync(0xffffffffu, v, o);
    return v;
}
__device__ __forceinline__ float warp_max(float v){
    #pragma unroll
    for (int o=16;o;o>>=1) v = fmaxf(v, __shfl_down_sync(0xffffffffu, v, o));
    return v;
}
__device__ __forceinline__ float warp_sum_all(float v){
    #pragma unroll
    for (int o=16;o;o>>=1) v += __shfl_xor_sync(0xffffffffu, v, o);
    return v;
}
template<bool MAXRED>
__device__ __forceinline__ float block_reduce(float v){
    __shared__ float sh[8];
    int tid = threadIdx.x;
    v = MAXRED ? warp_max(v) : warp_sum(v);
    __syncthreads();
    if ((tid & 31) == 0) sh[tid>>5] = v;
    __syncthreads();
    if (tid < 32){
        float a = (tid < 8) ? sh[tid] : (MAXRED ? -3.402823e38f : 0.f);
        a = MAXRED ? warp_max(a) : warp_sum(a);
        if (tid == 0) sh[0] = a;
    }
    __syncthreads();
    return sh[0];
}
__device__ __forceinline__ float gelu_f(float x){
    float x3 = x*x*x;
    return 0.5f*x*(1.f + tanhf(0.7978845608028654f*(x + 0.044715f*x3)));
}
__device__ __forceinline__ uint32_t sptr(const void* p){
    return (uint32_t)__cvta_generic_to_shared(p);
}
__device__ __forceinline__ uint32_t pk2(float lo, float hi){
    uint32_t r;
    asm("cvt.rn.bf16x2.f32 %0, %1, %2;" : "=r"(r) : "f"(hi), "f"(lo));
    return r;
}
// pack 4 floats -> 4 e4m3 bytes, byte0 = v0
__device__ __forceinline__ uint32_t pk4_e4m3(float v0, float v1, float v2, float v3){
    uint16_t h0, h1;
    asm("cvt.rn.satfinite.e4m3x2.f32 %0, %1, %2;" : "=h"(h0) : "f"(v1), "f"(v0));
    asm("cvt.rn.satfinite.e4m3x2.f32 %0, %1, %2;" : "=h"(h1) : "f"(v3), "f"(v2));
    return (uint32_t)h0 | ((uint32_t)h1 << 16);
}

#define CP16(dst, src) \
    asm volatile("cp.async.cg.shared.global [%0], [%1], 16;\n" :: "r"(dst), "l"(src))
#define CP_COMMIT()  asm volatile("cp.async.commit_group;\n" ::)
#define CP_WAIT1()   asm volatile("cp.async.wait_group 1;\n" ::)

#define LDSM4(r0,r1,r2,r3,addr) \
    asm volatile("ldmatrix.sync.aligned.m8n8.x4.shared.b16 {%0,%1,%2,%3}, [%4];" \
                 : "=r"(r0), "=r"(r1), "=r"(r2), "=r"(r3) : "r"(addr))
#define LDSM4T(r0,r1,r2,r3,addr) \
    asm volatile("ldmatrix.sync.aligned.m8n8.x4.trans.shared.b16 {%0,%1,%2,%3}, [%4];" \
                 : "=r"(r0), "=r"(r1), "=r"(r2), "=r"(r3) : "r"(addr))
#define MMA16816(c0,c1,c2,c3,a0,a1,a2,a3,b0,b1) \
    asm volatile( \
        "mma.sync.aligned.m16n8k16.row.col.f32.bf16.bf16.f32 " \
        "{%0,%1,%2,%3}, {%4,%5,%6,%7}, {%8,%9}, {%0,%1,%2,%3};\n" \
        : "+f"(c0), "+f"(c1), "+f"(c2), "+f"(c3) \
        : "r"(a0), "r"(a1), "r"(a2), "r"(a3), "r"(b0), "r"(b1))
#define MMAF8(c0,c1,c2,c3,a0,a1,a2,a3,b0,b1) \
    asm volatile( \
        "mma.sync.aligned.m16n8k32.row.col.f32.e4m3.e4m3.f32 " \
        "{%0,%1,%2,%3}, {%4,%5,%6,%7}, {%8,%9}, {%0,%1,%2,%3};\n" \
        : "+f"(c0), "+f"(c1), "+f"(c2), "+f"(c3) \
        : "r"(a0), "r"(a1), "r"(a2), "r"(a3), "r"(b0), "r"(b1))

// ---------------- merge kernels ----------------
__global__ void merge_g_all(const float* __restrict__ g1, const float* __restrict__ g2,
                            const float* __restrict__ gf,
                            const float* __restrict__ d_g1, const float* __restrict__ d_g2,
                            const float* __restrict__ d_gf,
                            const float* __restrict__ lam,
                            float* __restrict__ o1, float* __restrict__ o2,
                            float* __restrict__ of){
    int i = blockIdx.x*blockDim.x + threadIdx.x;
    float l0 = lam[0], l1 = lam[1];
    if (i < L_*D_){
        o1[i] = g1[i] + l0*d_g1[i] + l1*d_g1[L_*D_ + i];
        o2[i] = g2[i] + l0*d_g2[i] + l1*d_g2[L_*D_ + i];
    }
    if (i < D_)
        of[i] = gf[i] + l0*d_gf[i] + l1*d_gf[D_ + i];
}
__global__ void merge_emb_f8(const float* __restrict__ base,
                             const float* __restrict__ delta,
                             const float* __restrict__ lam,
                             uint32_t* __restrict__ outf8, size_t n){
    size_t n4 = n >> 2;
    float l0 = lam[0], l1 = lam[1];
    const float4* b4 = (const float4*)base;
    const float4* d0 = (const float4*)delta;
    const float4* d1 = (const float4*)(delta + n);
    for (size_t i = (size_t)blockIdx.x*blockDim.x + threadIdx.x; i < n4;
         i += (size_t)gridDim.x*blockDim.x){
        float4 b = b4[i], x0 = d0[i], x1 = d1[i];
        float r0 = b.x + l0*x0.x + l1*x1.x;
        float r1 = b.y + l0*x0.y + l1*x1.y;
        float r2 = b.z + l0*x0.z + l1*x1.z;
        float r3 = b.w + l0*x0.w + l1*x1.w;
        outf8[i] = pk4_e4m3(r0*256.f, r1*256.f, r2*256.f, r3*256.f);
    }
}
__global__ void tmerge_kernel(const float* __restrict__ base,
                              const float* __restrict__ delta,
                              const float* __restrict__ lam,
                              bf16* __restrict__ out,
                              int K, int Nw, size_t tstride){
    __shared__ float tile[32][33];
    int z = blockIdx.z;
    size_t mo = (size_t)z*K*Nw;
    float l0 = lam[0], l1 = lam[1];
    int n0 = blockIdx.x*32, k0 = blockIdx.y*32;
    #pragma unroll
    for (int j = 0; j < 32; j += 8){
        int k = k0 + threadIdx.y + j;
        int nn = n0 + threadIdx.x;
        size_t idx = mo + (size_t)k*Nw + nn;
        tile[threadIdx.y + j][threadIdx.x] =
            base[idx] + l0*delta[idx] + l1*delta[tstride + idx];
    }
    __syncthreads();
    #pragma unroll
    for (int j = 0; j < 32; j += 8){
        int nn = n0 + threadIdx.y + j;
        int k = k0 + threadIdx.x;
        out[mo + (size_t)nn*K + k] = __float2bfloat16(tile[threadIdx.x][threadIdx.y + j]);
    }
}
__global__ void tmerge_f8(const float* __restrict__ base,
                          const float* __restrict__ delta,
                          const float* __restrict__ lam,
                          uint32_t* __restrict__ out,
                          int K, int Nw, size_t tstride, float scale){
    __shared__ float tile[32][33];
    int z = blockIdx.z;
    size_t mo = (size_t)z*K*Nw;
    float l0 = lam[0], l1 = lam[1];
    int n0 = blockIdx.x*32, k0 = blockIdx.y*32;
    #pragma unroll
    for (int j = 0; j < 32; j += 8){
        int k = k0 + threadIdx.y + j;
        int nn = n0 + threadIdx.x;
        size_t idx = mo + (size_t)k*Nw + nn;
        tile[threadIdx.y + j][threadIdx.x] =
            base[idx] + l0*delta[idx] + l1*delta[tstride + idx];
    }
    __syncthreads();
    int tid = threadIdx.y*32 + threadIdx.x;
    int nn_l = tid >> 3;
    int kg = tid & 7;
    int nn = n0 + nn_l;
    int kk = kg*4;
    float v0 = tile[kk][nn_l]   * scale;
    float v1 = tile[kk+1][nn_l] * scale;
    float v2 = tile[kk+2][nn_l] * scale;
    float v3 = tile[kk+3][nn_l] * scale;
    out[((mo + (size_t)nn*K + k0) >> 2) + kg] = pk4_e4m3(v0, v1, v2, v3);
}

// ---------------- gather with on-the-fly merge ----------------
__global__ void gather_merge(const int* __restrict__ ids,
                             const float* __restrict__ emb,
                             const float* __restrict__ demb,
                             const float* __restrict__ lam,
                             float* __restrict__ x){
    int t = blockIdx.x;
    int id = ids[t];
    float l0 = lam[0], l1 = lam[1];
    const float4* b  = (const float4*)(emb  + (size_t)id*D_);
    const float4* e0 = (const float4*)(demb + (size_t)id*D_);
    const float4* e1 = (const float4*)(demb + (size_t)V_*D_ + (size_t)id*D_);
    float4* dst = (float4*)(x + (size_t)t*D_);
    for (int d = threadIdx.x; d < D_/4; d += blockDim.x){
        float4 bb = b[d], x0 = e0[d], x1 = e1[d], r;
        r.x = bb.x + l0*x0.x + l1*x1.x;
        r.y = bb.y + l0*x0.y + l1*x1.y;
        r.z = bb.z + l0*x0.z + l1*x1.z;
        r.w = bb.w + l0*x0.w + l1*x1.w;
        dst[d] = r;
    }
}

// ---------------- layernorm: warp-per-token (8 tok/CTA, no barriers) -----
__global__ void ln_kernel(const float* __restrict__ x,
                          const float* __restrict__ g,
                          bf16* __restrict__ out){
    const int warp = threadIdx.x >> 5, lane = threadIdx.x & 31;
    const int t = blockIdx.x*8 + warp;
    const float4* xr = (const float4*)(x + (size_t)t*D_);
    const float4* gr = (const float4*)g;
    float4 v[8];
    float s = 0.f, ss = 0.f;
    #pragma unroll
    for (int j = 0; j < 8; j++){
        v[j] = xr[lane + j*32];
        s  += v[j].x + v[j].y + v[j].z + v[j].w;
        ss += v[j].x*v[j].x + v[j].y*v[j].y + v[j].z*v[j].z + v[j].w*v[j].w;
    }
    s  = warp_sum_all(s);
    ss = warp_sum_all(ss);
    float mu  = s * (1.f/D_);
    float var = ss * (1.f/D_) - mu*mu;
    float inv = rsqrtf(var + 1e-5f);
    uint2* orow = (uint2*)(out + (size_t)t*D_);
    #pragma unroll
    for (int j = 0; j < 8; j++){
        float4 gg = gr[lane + j*32];
        uint2 o2;
        o2.x = pk2((v[j].x-mu)*inv*gg.x, (v[j].y-mu)*inv*gg.y);
        o2.y = pk2((v[j].z-mu)*inv*gg.z, (v[j].w-mu)*inv*gg.w);
        orow[lane + j*32] = o2;
    }
}
// LN -> e4m3 packed, scale 4 (warp-per-token)
__global__ void ln_f8_kernel(const float* __restrict__ x,
                             const float* __restrict__ g,
                             uint32_t* __restrict__ out){
    const int warp = threadIdx.x >> 5, lane = threadIdx.x & 31;
    const int t = blockIdx.x*8 + warp;
    const float4* xr = (const float4*)(x + (size_t)t*D_);
    const float4* gr = (const float4*)g;
    float4 v[8];
    float s = 0.f, ss = 0.f;
    #pragma unroll
    for (int j = 0; j < 8; j++){
        v[j] = xr[lane + j*32];
        s  += v[j].x + v[j].y + v[j].z + v[j].w;
        ss += v[j].x*v[j].x + v[j].y*v[j].y + v[j].z*v[j].z + v[j].w*v[j].w;
    }
    s  = warp_sum_all(s);
    ss = warp_sum_all(ss);
    float mu  = s * (1.f/D_);
    float var = ss * (1.f/D_) - mu*mu;
    float inv = rsqrtf(var + 1e-5f) * 4.f;
    uint32_t* orow = out + (size_t)t*(D_/4);
    #pragma unroll
    for (int j = 0; j < 8; j++){
        float4 gg = gr[lane + j*32];
        orow[lane + j*32] = pk4_e4m3((v[j].x-mu)*inv*gg.x, (v[j].y-mu)*inv*gg.y,
                                     (v[j].z-mu)*inv*gg.z, (v[j].w-mu)*inv*gg.w);
    }
}

// ================= bf16 GEMM (NT, 2-stage cp.async + ldmatrix) ============
#define PAD 40

template<int ACT, int RES, int OUTBF>
__global__ void __launch_bounds__(256) hgemm(int M, int N, int K,
                        const bf16* __restrict__ A,
                        const bf16* __restrict__ Bt,
                        const float* __restrict__ Res,
                        void* __restrict__ Cout){
    __shared__ __align__(16) bf16 As[2][128*PAD];
    __shared__ __align__(16) bf16 Bs[2][128*PAD];

    const int tid  = threadIdx.x;
    const int lane = tid & 31;
    const int warp = tid >> 5;
    const int g    = lane >> 2;
    const int t    = lane & 3;
    const int wm   = warp >> 1;
    const int wn   = warp & 1;
    const int row0 = blockIdx.x * 128;
    const int col0 = blockIdx.y * 128;

    float c[2][8][4];
    #pragma unroll
    for (int i=0;i<2;i++)
        #pragma unroll
        for (int j=0;j<8;j++)
            #pragma unroll
            for (int k=0;k<4;k++) c[i][j][k]=0.f;

    const int r1 = tid >> 2;
    const int c8 = (tid & 3) * 8;
    const bf16* Ag0 = A  + (size_t)(row0 + r1)*K + c8;
    const bf16* Ag1 = A  + (size_t)(row0 + r1 + 64)*K + c8;
    const bf16* Bg0 = Bt + (size_t)(col0 + r1)*K + c8;
    const bf16* Bg1 = Bt + (size_t)(col0 + r1 + 64)*K + c8;
    const uint32_t sa0 = sptr(&As[0][r1*PAD + c8]);
    const uint32_t sa1 = sptr(&As[0][(r1+64)*PAD + c8]);
    const uint32_t sb0 = sptr(&Bs[0][r1*PAD + c8]);
    const uint32_t sb1 = sptr(&Bs[0][(r1+64)*PAD + c8]);
    const uint32_t SS = 128*PAD*2;

    uint32_t aAddr[2];
    #pragma unroll
    for (int mt = 0; mt < 2; mt++)
        aAddr[mt] = sptr(&As[0][(wm*32 + mt*16 + (lane & 15))*PAD + (lane >> 4)*8]);
    uint32_t bAddr[4];
    #pragma unroll
    for (int bt = 0; bt < 4; bt++)
        bAddr[bt] = sptr(&Bs[0][(wn*64 + bt*16 + ((lane>>4)&1)*8 + (lane&7))*PAD
                                + ((lane>>3)&1)*8]);

    {
        CP16(sa0, Ag0); CP16(sa1, Ag1);
        CP16(sb0, Bg0); CP16(sb1, Bg1);
        CP_COMMIT();
    }

    const int KT = K >> 5;
    int s = 0;
    for (int kt = 0; kt < KT; kt++){
        if (kt + 1 < KT){
            const int ko = (kt + 1) << 5;
            const uint32_t so = (s ^ 1) * SS;
            CP16(sa0 + so, Ag0 + ko); CP16(sa1 + so, Ag1 + ko);
            CP16(sb0 + so, Bg0 + ko); CP16(sb1 + so, Bg1 + ko);
        }
        CP_COMMIT();
        CP_WAIT1();
        __syncthreads();

        const uint32_t sb = s * SS;
        #pragma unroll
        for (int ks = 0; ks < 2; ks++){
            const uint32_t kb = sb + ks*32;
            uint32_t a[2][4];
            #pragma unroll
            for (int mt = 0; mt < 2; mt++)
                LDSM4(a[mt][0], a[mt][1], a[mt][2], a[mt][3], aAddr[mt] + kb);
            uint32_t bb[4][4];
            #pragma unroll
            for (int bt = 0; bt < 4; bt++)
                LDSM4(bb[bt][0], bb[bt][1], bb[bt][2], bb[bt][3], bAddr[bt] + kb);
            #pragma unroll
            for (int mt = 0; mt < 2; mt++)
                #pragma unroll
                for (int nt = 0; nt < 8; nt++){
                    const int bt = nt >> 1, su = (nt & 1) * 2;
                    MMA16816(c[mt][nt][0], c[mt][nt][1], c[mt][nt][2], c[mt][nt][3],
                             a[mt][0], a[mt][1], a[mt][2], a[mt][3],
                             bb[bt][su], bb[bt][su+1]);
                }
        }
        __syncthreads();
        s ^= 1;
    }

    float* Cf = (float*)Cout;
    bf16*  Ch = (bf16*)Cout;
    #pragma unroll
    for (int mt = 0; mt < 2; mt++){
        int r0 = row0 + wm*32 + mt*16 + g;
        #pragma unroll
        for (int nt = 0; nt < 8; nt++){
            int cc = col0 + wn*64 + nt*8 + 2*t;
            float v0 = c[mt][nt][0], v1 = c[mt][nt][1];
            float v2 = c[mt][nt][2], v3 = c[mt][nt][3];
            if (RES){
                v0 += Res[(size_t)r0*N + cc];
                v1 += Res[(size_t)r0*N + cc + 1];
                v2 += Res[(size_t)(r0+8)*N + cc];
                v3 += Res[(size_t)(r0+8)*N + cc + 1];
            }
            if (ACT){
                v0 = gelu_f(v0); v1 = gelu_f(v1);
                v2 = gelu_f(v2); v3 = gelu_f(v3);
            }
            if (OUTBF){
                *(__nv_bfloat162*)&Ch[(size_t)r0*N + cc]     = __floats2bfloat162_rn(v0, v1);
                *(__nv_bfloat162*)&Ch[(size_t)(r0+8)*N + cc] = __floats2bfloat162_rn(v2, v3);
            } else {
                Cf[(size_t)r0*N + cc]         = v0;
                Cf[(size_t)r0*N + cc + 1]     = v1;
                Cf[(size_t)(r0+8)*N + cc]     = v2;
                Cf[(size_t)(r0+8)*N + cc + 1] = v3;
            }
        }
    }
}

// ================= FP8 GEMM (2-stage, generic epilogue) ===================
// OUT: 0 = fp32 (+Res), 2 = packed e4m3 (x osc)
template<int ACT, int RES, int OUT>
__global__ void __launch_bounds__(256) f8gemm(int K16, int N,
                        const bf16* __restrict__ A,
                        const bf16* __restrict__ Bt,
                        const float* __restrict__ Res,
                        void* __restrict__ Cout,
                        float dsc, float osc){
    __shared__ __align__(16) bf16 As[2][128*PAD];
    __shared__ __align__(16) bf16 Bs[2][128*PAD];

    const int tid  = threadIdx.x;
    const int lane = tid & 31;
    const int warp = tid >> 5;
    const int g    = lane >> 2;
    const int t    = lane & 3;
    const int wm   = warp >> 1;
    const int wn   = warp & 1;
    const int row0 = blockIdx.x * 128;
    const int col0 = blockIdx.y * 128;
    const int K = K16;

    float c[2][8][4];
    #pragma unroll
    for (int i=0;i<2;i++)
        #pragma unroll
        for (int j=0;j<8;j++)
            #pragma unroll
            for (int k=0;k<4;k++) c[i][j][k]=0.f;

    const int r1 = tid >> 2;
    const int c8 = (tid & 3) * 8;
    const bf16* Ag0 = A  + (size_t)(row0 + r1)*K + c8;
    const bf16* Ag1 = A  + (size_t)(row0 + r1 + 64)*K + c8;
    const bf16* Bg0 = Bt + (size_t)(col0 + r1)*K + c8;
    const bf16* Bg1 = Bt + (size_t)(col0 + r1 + 64)*K + c8;
    const uint32_t sa0 = sptr(&As[0][r1*PAD + c8]);
    const uint32_t sa1 = sptr(&As[0][(r1+64)*PAD + c8]);
    const uint32_t sb0 = sptr(&Bs[0][r1*PAD + c8]);
    const uint32_t sb1 = sptr(&Bs[0][(r1+64)*PAD + c8]);
    const uint32_t SS = 128*PAD*2;

    uint32_t aAddr[2];
    #pragma unroll
    for (int mt = 0; mt < 2; mt++)
        aAddr[mt] = sptr(&As[0][(wm*32 + mt*16 + (lane & 15))*PAD + (lane >> 4)*8]);
    uint32_t bAddr[4];
    #pragma unroll
    for (int bt = 0; bt < 4; bt++)
        bAddr[bt] = sptr(&Bs[0][(wn*64 + bt*16 + ((lane>>4)&1)*8 + (lane&7))*PAD
                                + ((lane>>3)&1)*8]);

    {
        CP16(sa0, Ag0); CP16(sa1, Ag1);
        CP16(sb0, Bg0); CP16(sb1, Bg1);
        CP_COMMIT();
    }

    const int KT = K >> 5;
    int s = 0;
    for (int kt = 0; kt < KT; kt++){
        if (kt + 1 < KT){
            const int ko = (kt + 1) << 5;
            const uint32_t so = (s ^ 1) * SS;
            CP16(sa0 + so, Ag0 + ko); CP16(sa1 + so, Ag1 + ko);
            CP16(sb0 + so, Bg0 + ko); CP16(sb1 + so, Bg1 + ko);
        }
        CP_COMMIT();
        CP_WAIT1();
        __syncthreads();

        const uint32_t sb = s * SS;
        #pragma unroll
        for (int ks = 0; ks < 2; ks++){
            const uint32_t kb = sb + ks*32;
            uint32_t a[2][4];
            #pragma unroll
            for (int mt = 0; mt < 2; mt++)
                LDSM4(a[mt][0], a[mt][1], a[mt][2], a[mt][3], aAddr[mt] + kb);
            uint32_t bb[4][4];
            #pragma unroll
            for (int bt = 0; bt < 4; bt++)
                LDSM4(bb[bt][0], bb[bt][1], bb[bt][2], bb[bt][3], bAddr[bt] + kb);
            #pragma unroll
            for (int mt = 0; mt < 2; mt++)
                #pragma unroll
                for (int nt = 0; nt < 8; nt++){
                    const int bt = nt >> 1, su = (nt & 1) * 2;
                    MMAF8(c[mt][nt][0], c[mt][nt][1], c[mt][nt][2], c[mt][nt][3],
                          a[mt][0], a[mt][1], a[mt][2], a[mt][3],
                          bb[bt][su], bb[bt][su+1]);
                }
        }
        __syncthreads();
        s ^= 1;
    }

    float* Cf = (float*)Cout;
    uint32_t* C8 = (uint32_t*)Cout;
    #pragma unroll
    for (int mt = 0; mt < 2; mt++){
        int r0 = row0 + wm*32 + mt*16 + g;
        #pragma unroll
        for (int nt = 0; nt < 8; nt++){
            int cc = col0 + wn*64 + nt*8 + 2*t;
            float v0 = c[mt][nt][0]*dsc, v1 = c[mt][nt][1]*dsc;
            float v2 = c[mt][nt][2]*dsc, v3 = c[mt][nt][3]*dsc;
            if (RES){
                v0 += Res[(size_t)r0*N + cc];
                v1 += Res[(size_t)r0*N + cc + 1];
                v2 += Res[(size_t)(r0+8)*N + cc];
                v3 += Res[(size_t)(r0+8)*N + cc + 1];
            }
            if (ACT){
                v0 = gelu_f(v0); v1 = gelu_f(v1);
                v2 = gelu_f(v2); v3 = gelu_f(v3);
            }
            if (OUT == 2){
                v0 *= osc; v1 *= osc; v2 *= osc; v3 *= osc;
                float u0 = __shfl_xor_sync(0xffffffffu, v0, 1);
                float u1 = __shfl_xor_sync(0xffffffffu, v1, 1);
                float u2 = __shfl_xor_sync(0xffffffffu, v2, 1);
                float u3 = __shfl_xor_sync(0xffffffffu, v3, 1);
                if ((t & 1) == 0){
                    size_t i0 = ((size_t)r0*N + cc) >> 2;
                    size_t i1 = ((size_t)(r0+8)*N + cc) >> 2;
                    C8[i0] = pk4_e4m3(v0, v1, u0, u1);
                    C8[i1] = pk4_e4m3(v2, v3, u2, u3);
                }
            } else {
                Cf[(size_t)r0*N + cc]         = v0;
                Cf[(size_t)r0*N + cc + 1]     = v1;
                Cf[(size_t)(r0+8)*N + cc]     = v2;
                Cf[(size_t)(r0+8)*N + cc + 1] = v3;
            }
        }
    }
}

// ============ FP8 logits GEMM (2-stage) with fused logsumexp ==============
__global__ void __launch_bounds__(256) f8gemm_lse(int K16,
                        const bf16* __restrict__ A,
                        const bf16* __restrict__ Bt,
                        const int* __restrict__ labels,
                        float2* __restrict__ part,
                        float* __restrict__ tgtlog){
    __shared__ __align__(16) bf16 As[2][128*PAD];
    __shared__ __align__(16) bf16 Bs[2][128*PAD];
    __shared__ float2 red[2][128];
    __shared__ float  tgv[2][128];
    __shared__ float  tgf[2][128];

    const int tid  = threadIdx.x;
    const int lane = tid & 31;
    const int warp = tid >> 5;
    const int g    = lane >> 2;
    const int t    = lane & 3;
    const int wm   = warp >> 1;
    const int wn   = warp & 1;
    const int row0 = blockIdx.x * 128;
    const int col0 = blockIdx.y * 128;
    const int K = K16;

    float c[2][8][4];
    #pragma unroll
    for (int i=0;i<2;i++)
        #pragma unroll
        for (int j=0;j<8;j++)
            #pragma unroll
            for (int k=0;k<4;k++) c[i][j][k]=0.f;

    const int r1 = tid >> 2;
    const int c8 = (tid & 3) * 8;
    const bf16* Ag0 = A  + (size_t)(row0 + r1)*K + c8;
    const bf16* Ag1 = A  + (size_t)(row0 + r1 + 64)*K + c8;
    const bf16* Bg0 = Bt + (size_t)(col0 + r1)*K + c8;
    const bf16* Bg1 = Bt + (size_t)(col0 + r1 + 64)*K + c8;
    const uint32_t sa0 = sptr(&As[0][r1*PAD + c8]);
    const uint32_t sa1 = sptr(&As[0][(r1+64)*PAD + c8]);
    const uint32_t sb0 = sptr(&Bs[0][r1*PAD + c8]);
    const uint32_t sb1 = sptr(&Bs[0][(r1+64)*PAD + c8]);
    const uint32_t SS = 128*PAD*2;

    uint32_t aAddr[2];
    #pragma unroll
    for (int mt = 0; mt < 2; mt++)
        aAddr[mt] = sptr(&As[0][(wm*32 + mt*16 + (lane & 15))*PAD + (lane >> 4)*8]);
    uint32_t bAddr[4];
    #pragma unroll
    for (int bt = 0; bt < 4; bt++)
        bAddr[bt] = sptr(&Bs[0][(wn*64 + bt*16 + ((lane>>4)&1)*8 + (lane&7))*PAD
                                + ((lane>>3)&1)*8]);

    {
        CP16(sa0, Ag0); CP16(sa1, Ag1);
        CP16(sb0, Bg0); CP16(sb1, Bg1);
        CP_COMMIT();
    }

    const int KT = K >> 5;
    int s = 0;
    for (int kt = 0; kt < KT; kt++){
        if (kt + 1 < KT){
            const int ko = (kt + 1) << 5;
            const uint32_t so = (s ^ 1) * SS;
            CP16(sa0 + so, Ag0 + ko); CP16(sa1 + so, Ag1 + ko);
            CP16(sb0 + so, Bg0 + ko); CP16(sb1 + so, Bg1 + ko);
        }
        CP_COMMIT();
        CP_WAIT1();
        __syncthreads();

        const uint32_t sb = s * SS;
        #pragma unroll
        for (int ks = 0; ks < 2; ks++){
            const uint32_t kb = sb + ks*32;
            uint32_t a[2][4];
            #pragma unroll
            for (int mt = 0; mt < 2; mt++)
                LDSM4(a[mt][0], a[mt][1], a[mt][2], a[mt][3], aAddr[mt] + kb);
            uint32_t bb[4][4];
            #pragma unroll
            for (int bt = 0; bt < 4; bt++)
                LDSM4(bb[bt][0], bb[bt][1], bb[bt][2], bb[bt][3], bAddr[bt] + kb);
            #pragma unroll
            for (int mt = 0; mt < 2; mt++)
                #pragma unroll
                for (int nt = 0; nt < 8; nt++){
                    const int bt = nt >> 1, su = (nt & 1) * 2;
                    MMAF8(c[mt][nt][0], c[mt][nt][1], c[mt][nt][2], c[mt][nt][3],
                          a[mt][0], a[mt][1], a[mt][2], a[mt][3],
                          bb[bt][su], bb[bt][su+1]);
                }
        }
        __syncthreads();
        s ^= 1;
    }

    const float scale = 1.f/1024.f;
    #pragma unroll
    for (int mt = 0; mt < 2; mt++){
        #pragma unroll
        for (int half = 0; half < 2; half++){
            const int rowi = wm*32 + mt*16 + half*8 + g;
            const int token = row0 + rowi;
            const int ss2 = token & (S_-1);
            const int tgt = (ss2 == S_-1) ? -1
                          : labels[(token >> 10)*S_ + ss2 + 1];
            float rm = -1e30f;
            float v[16];
            #pragma unroll
            for (int nt = 0; nt < 8; nt++){
                v[2*nt]   = c[mt][nt][2*half]   * scale;
                v[2*nt+1] = c[mt][nt][2*half+1] * scale;
                rm = fmaxf(rm, fmaxf(v[2*nt], v[2*nt+1]));
            }
            float rs = 0.f, tv = 0.f, tf = 0.f;
            #pragma unroll
            for (int nt = 0; nt < 8; nt++){
                rs += __expf(v[2*nt] - rm) + __expf(v[2*nt+1] - rm);
                int col = col0 + wn*64 + nt*8 + 2*t;
                if (col   == tgt){ tv = v[2*nt];   tf = 1.f; }
                if (col+1 == tgt){ tv = v[2*nt+1]; tf = 1.f; }
            }
            #pragma unroll
            for (int o = 1; o <= 2; o <<= 1){
                float om = __shfl_xor_sync(0xffffffffu, rm, o);
                float os = __shfl_xor_sync(0xffffffffu, rs, o);
                float nm = fmaxf(rm, om);
                rs = rs*__expf(rm - nm) + os*__expf(om - nm);
                rm = nm;
                tv += __shfl_xor_sync(0xffffffffu, tv, o);
                tf += __shfl_xor_sync(0xffffffffu, tf, o);
            }
            if (t == 0){
                red[wn][rowi] = make_float2(rm, rs);
                tgv[wn][rowi] = tv;
                tgf[wn][rowi] = tf;
            }
        }
    }
    __syncthreads();
    if (tid < 128){
        float2 p0 = red[0][tid], p1 = red[1][tid];
        float m = fmaxf(p0.x, p1.x);
        float sm = p0.y*__expf(p0.x - m) + p1.y*__expf(p1.x - m);
        int token = row0 + tid;
        part[(size_t)token*256 + blockIdx.y] = make_float2(m, sm);
        if (tgf[0][tid] + tgf[1][tid] > 0.5f)
            tgtlog[token] = tgv[0][tid] + tgv[1][tid];
    }
}

// ================= fused flash attention ==================================
#define QPAD 72

__global__ void __launch_bounds__(256) flash_attn(const bf16* __restrict__ qkv,
                                                  bf16* __restrict__ out){
    __shared__ __align__(16) bf16 Qs[128*QPAD];
    __shared__ __align__(16) bf16 Ks[2][64*QPAD];
    __shared__ __align__(16) bf16 Vs[2][64*QPAD];

    const int tid  = threadIdx.x;
    const int lane = tid & 31;
    const int warp = tid >> 5;
    const int g    = lane >> 2;
    const int t    = lane & 3;
    const int qt   = gridDim.x - 1 - blockIdx.x;   // longest-first scheduling
    const int bh   = blockIdx.y;
    const int b    = bh >> 4, h = bh & 15;
    const int q0   = qt * 128;

    const size_t tok0 = (size_t)b * S_;
    const bf16* Qg = qkv + (tok0 + q0)*(3*D_) + h*HD_;
    const bf16* Kg = qkv + tok0*(3*D_) + D_   + h*HD_;
    const bf16* Vg = qkv + tok0*(3*D_) + 2*D_ + h*HD_;

    {
        #pragma unroll
        for (int j = 0; j < 4; j++){
            int ch = tid + j*256;
            int r = ch >> 3, c = (ch & 7)*8;
            CP16(sptr(&Qs[r*QPAD + c]), Qg + (size_t)r*(3*D_) + c);
        }
        #pragma unroll
        for (int j = 0; j < 2; j++){
            int ch = tid + j*256;
            int r = ch >> 3, c = (ch & 7)*8;
            CP16(sptr(&Ks[0][r*QPAD + c]), Kg + (size_t)r*(3*D_) + c);
            CP16(sptr(&Vs[0][r*QPAD + c]), Vg + (size_t)r*(3*D_) + c);
        }
        CP_COMMIT();
    }

    float m0 = -1e30f, m1 = -1e30f, l0 = 0.f, l1 = 0.f;
    float o[8][4];
    #pragma unroll
    for (int i=0;i<8;i++){ o[i][0]=0.f; o[i][1]=0.f; o[i][2]=0.f; o[i][3]=0.f; }

    const uint32_t aQ = sptr(&Qs[(warp*16 + (lane & 15))*QPAD + (lane >> 4)*8]);
    uint32_t kA[4], vA[4];
    #pragma unroll
    for (int bt = 0; bt < 4; bt++)
        kA[bt] = sptr(&Ks[0][(bt*16 + ((lane>>4)&1)*8 + (lane&7))*QPAD
                             + ((lane>>3)&1)*8]);
    #pragma unroll
    for (int dt = 0; dt < 4; dt++)
        vA[dt] = sptr(&Vs[0][(((lane>>3)&1)*8 + (lane&7))*QPAD
                             + dt*16 + ((lane>>4)&1)*8]);
    const uint32_t KVS = 64*QPAD*2;

    const int nkt = 2*qt + 2;
    int s = 0;
    for (int kt = 0; kt < nkt; kt++){
        if (kt + 1 < nkt){
            const bf16* Kg2 = Kg + (size_t)(kt+1)*64*(3*D_);
            const bf16* Vg2 = Vg + (size_t)(kt+1)*64*(3*D_);
            bf16* ksm = &Ks[s^1][0];
            bf16* vsm = &Vs[s^1][0];
            #pragma unroll
            for (int j = 0; j < 2; j++){
                int ch = tid + j*256;
                int r = ch >> 3, c = (ch & 7)*8;
                CP16(sptr(ksm + r*QPAD + c), Kg2 + (size_t)r*(3*D_) + c);
                CP16(sptr(vsm + r*QPAD + c), Vg2 + (size_t)r*(3*D_) + c);
            }
        }
        CP_COMMIT();
        CP_WAIT1();
        __syncthreads();

        const uint32_t so = s * KVS;

        float sc[8][4];
        #pragma unroll
        for (int i=0;i<8;i++){ sc[i][0]=0.f; sc[i][1]=0.f; sc[i][2]=0.f; sc[i][3]=0.f; }
        #pragma unroll
        for (int kk = 0; kk < 4; kk++){
            uint32_t a0,a1,a2,a3;
            LDSM4(a0,a1,a2,a3, aQ + kk*32);
            uint32_t bb[4][4];
            #pragma unroll
            for (int bt = 0; bt < 4; bt++)
                LDSM4(bb[bt][0],bb[bt][1],bb[bt][2],bb[bt][3], kA[bt] + so + kk*32);
            #pragma unroll
            for (int nt = 0; nt < 8; nt++){
                const int bt = nt >> 1, su = (nt & 1)*2;
                MMA16816(sc[nt][0],sc[nt][1],sc[nt][2],sc[nt][3],
                         a0,a1,a2,a3, bb[bt][su], bb[bt][su+1]);
            }
        }

        const int qrow0 = q0 + warp*16 + g;
        const int qrow1 = qrow0 + 8;
        const bool masked = (kt >= 2*qt);
        #pragma unroll
        for (int nt = 0; nt < 8; nt++){
            int col = kt*64 + nt*8 + 2*t;
            #pragma unroll
            for (int u = 0; u < 4; u++) sc[nt][u] *= 0.125f;
            if (masked){
                if (col   > qrow0) sc[nt][0] = -1e30f;
                if (col+1 > qrow0) sc[nt][1] = -1e30f;
                if (col   > qrow1) sc[nt][2] = -1e30f;
                if (col+1 > qrow1) sc[nt][3] = -1e30f;
            }
        }

        float tm0 = -1e30f, tm1 = -1e30f;
        #pragma unroll
        for (int nt = 0; nt < 8; nt++){
            tm0 = fmaxf(tm0, fmaxf(sc[nt][0], sc[nt][1]));
            tm1 = fmaxf(tm1, fmaxf(sc[nt][2], sc[nt][3]));
        }
        tm0 = fmaxf(tm0, __shfl_xor_sync(0xffffffffu, tm0, 1));
        tm0 = fmaxf(tm0, __shfl_xor_sync(0xffffffffu, tm0, 2));
        tm1 = fmaxf(tm1, __shfl_xor_sync(0xffffffffu, tm1, 1));
        tm1 = fmaxf(tm1, __shfl_xor_sync(0xffffffffu, tm1, 2));
        float nm0 = fmaxf(m0, tm0), nm1 = fmaxf(m1, tm1);
        float al0 = __expf(m0 - nm0), al1 = __expf(m1 - nm1);
        m0 = nm0; m1 = nm1;
        float ps0 = 0.f, ps1 = 0.f;
        #pragma unroll
        for (int nt = 0; nt < 8; nt++){
            sc[nt][0] = __expf(sc[nt][0] - nm0);
            sc[nt][1] = __expf(sc[nt][1] - nm0);
            sc[nt][2] = __expf(sc[nt][2] - nm1);
            sc[nt][3] = __expf(sc[nt][3] - nm1);
            ps0 += sc[nt][0] + sc[nt][1];
            ps1 += sc[nt][2] + sc[nt][3];
        }
        l0 = l0*al0 + ps0;
        l1 = l1*al1 + ps1;
        #pragma unroll
        for (int dt = 0; dt < 8; dt++){
            o[dt][0] *= al0; o[dt][1] *= al0;
            o[dt][2] *= al1; o[dt][3] *= al1;
        }

        #pragma unroll
        for (int kk = 0; kk < 4; kk++){
            uint32_t a0 = pk2(sc[2*kk][0],   sc[2*kk][1]);
            uint32_t a1 = pk2(sc[2*kk][2],   sc[2*kk][3]);
            uint32_t a2 = pk2(sc[2*kk+1][0], sc[2*kk+1][1]);
            uint32_t a3 = pk2(sc[2*kk+1][2], sc[2*kk+1][3]);
            uint32_t vv[4][4];
            #pragma unroll
            for (int dt = 0; dt < 4; dt++)
                LDSM4T(vv[dt][0],vv[dt][1],vv[dt][2],vv[dt][3],
                       vA[dt] + so + kk*16*QPAD*2);
            #pragma unroll
            for (int nt = 0; nt < 8; nt++){
                const int dt = nt >> 1, su = (nt & 1)*2;
                MMA16816(o[nt][0],o[nt][1],o[nt][2],o[nt][3],
                         a0,a1,a2,a3, vv[dt][su], vv[dt][su+1]);
            }
        }
        __syncthreads();
        s ^= 1;
    }

    l0 += __shfl_xor_sync(0xffffffffu, l0, 1);
    l0 += __shfl_xor_sync(0xffffffffu, l0, 2);
    l1 += __shfl_xor_sync(0xffffffffu, l1, 1);
    l1 += __shfl_xor_sync(0xffffffffu, l1, 2);
    float r0 = 1.f/l0, r1 = 1.f/l1;
    const int row0 = q0 + warp*16 + g;
    bf16* O0 = out + (tok0 + row0)*D_ + h*HD_;
    bf16* O1 = out + (tok0 + row0 + 8)*D_ + h*HD_;
    #pragma unroll
    for (int dt = 0; dt < 8; dt++){
        int cc = dt*8 + 2*t;
        *(__nv_bfloat162*)&O0[cc] = __floats2bfloat162_rn(o[dt][0]*r0, o[dt][1]*r0);
        *(__nv_bfloat162*)&O1[cc] = __floats2bfloat162_rn(o[dt][2]*r1, o[dt][3]*r1);
    }
}

// ---------------- NLL final ----------------
__global__ void nll_final(const float2* __restrict__ part,
                          const float* __restrict__ tgtlog,
                          float* __restrict__ nll){
    int t = blockIdx.x, tid = threadIdx.x;
    int ss = t & (S_-1);
    if (ss == S_-1){ if (tid == 0) nll[t] = 0.f; return; }
    float2 p = (tid < V_/128) ? part[(size_t)t*256 + tid]
                              : make_float2(-1e30f, 0.f);
    float M = block_reduce<true>(p.x);
    float S = block_reduce<false>(p.y * __expf(p.x - M));
    if (tid == 0) nll[t] = logf(S) + M - tgtlog[t];
}

// ---------------- final mean ----------------
__global__ void final_reduce(const float* __restrict__ nll, float* __restrict__ out){
    float s = 0.f;
    for (int t = threadIdx.x; t < N_; t += 256)
        if ((t & (S_-1)) != S_-1) s += nll[t];
    s = block_reduce<false>(s);
    if (threadIdx.x == 0) out[0] = s * (1.f/(B_*(S_-1)));
}

// ---------------- side stream (created at static init) ----------------
struct SideStream {
    cudaStream_t s2;
    cudaEvent_t fork, join, join2;
    SideStream(){
        cudaStreamCreateWithFlags(&s2, cudaStreamNonBlocking);
        cudaEventCreateWithFlags(&fork,  cudaEventDisableTiming);
        cudaEventCreateWithFlags(&join,  cudaEventDisableTiming);
        cudaEventCreateWithFlags(&join2, cudaEventDisableTiming);
    }
};
static SideStream g_ss;

// ---------------- host launch ----------------
static inline int mgrid(size_t n){
    size_t n4 = n >> 2;
    return (int)((n4 + 255) / 256);
}

extern "C" void kernel_launch(void* const* d_in, const int* in_sizes, int n_in,
                              void* d_out, int out_size){
    const int*   ids    = (const int*)  d_in[0];
    const int*   labels = (const int*)  d_in[1];
    const float* lam    = (const float*)d_in[2];
    const float* emb    = (const float*)d_in[3];
    const float* Wqkv   = (const float*)d_in[4];
    const float* Wo     = (const float*)d_in[5];
    const float* W1     = (const float*)d_in[6];
    const float* W2     = (const float*)d_in[7];
    const float* g1     = (const float*)d_in[8];
    const float* g2     = (const float*)d_in[9];
    const float* gf     = (const float*)d_in[10];
    const float* d_emb  = (const float*)d_in[11];
    const float* d_Wqkv = (const float*)d_in[12];
    const float* d_Wo   = (const float*)d_in[13];
    const float* d_W1   = (const float*)d_in[14];
    const float* d_W2   = (const float*)d_in[15];
    const float* d_g1   = (const float*)d_in[16];
    const float* d_g2   = (const float*)d_in[17];
    const float* d_gf   = (const float*)d_in[18];

    float *p_g1, *p_g2, *p_gf, *p_x, *p_tgt, *p_nll;
    bf16  *p_WqkvT, *p_WoT, *p_a, *p_o, *p_qkvh;
    uint32_t *p_embf8, *p_af8, *p_W18, *p_W28, *p_ff8;
    float2 *p_part;
    cudaGetSymbolAddress((void**)&p_embf8,  g_embf8);
    cudaGetSymbolAddress((void**)&p_WqkvT,  g_WqkvT);
    cudaGetSymbolAddress((void**)&p_WoT,    g_WoT);
    cudaGetSymbolAddress((void**)&p_W18,    g_W18);
    cudaGetSymbolAddress((void**)&p_W28,    g_W28);
    cudaGetSymbolAddress((void**)&p_g1,     g_g1);
    cudaGetSymbolAddress((void**)&p_g2,     g_g2);
    cudaGetSymbolAddress((void**)&p_gf,     g_gfm);
    cudaGetSymbolAddress((void**)&p_x,      g_x);
    cudaGetSymbolAddress((void**)&p_a,      g_a);
    cudaGetSymbolAddress((void**)&p_af8,    g_af8);
    cudaGetSymbolAddress((void**)&p_qkvh,   g_qkvh);
    cudaGetSymbolAddress((void**)&p_o,      g_o);
    cudaGetSymbolAddress((void**)&p_ff8,    g_ff8);
    cudaGetSymbolAddress((void**)&p_part,   g_part);
    cudaGetSymbolAddress((void**)&p_tgt,    g_tgt);
    cudaGetSymbolAddress((void**)&p_nll,    g_nll);

    size_t n;
    dim3 t328(32, 8);

    // ---- fork: side stream runs BW-bound merges needed late ----
    cudaEventRecord(g_ss.fork, 0);
    cudaStreamWaitEvent(g_ss.s2, g_ss.fork, 0);
    tmerge_kernel<<<dim3(D_/32, D_/32, L_), t328, 0, g_ss.s2>>>(
        Wo, d_Wo, lam, p_WoT, D_, D_, (size_t)L_*D_*D_);
    tmerge_f8<<<dim3(DFF_/32, D_/32, L_), t328, 0, g_ss.s2>>>(
        W1, d_W1, lam, p_W18, D_, DFF_, (size_t)L_*D_*DFF_, 256.f);
    tmerge_f8<<<dim3(D_/32, DFF_/32, L_), t328, 0, g_ss.s2>>>(
        W2, d_W2, lam, p_W28, DFF_, D_, (size_t)L_*DFF_*D_, 256.f);
    cudaEventRecord(g_ss.join, g_ss.s2);
    n = (size_t)V_*D_;
    merge_emb_f8<<<mgrid(n),256,0,g_ss.s2>>>(emb, d_emb, lam, p_embf8, n);
    cudaEventRecord(g_ss.join2, g_ss.s2);

    // ---- main stream: what layer 0's prefix needs ----
    gather_merge<<<N_, 256>>>(ids, emb, d_emb, lam, p_x);
    merge_g_all<<<(L_*D_ + 255)/256, 256>>>(g1, g2, gf, d_g1, d_g2, d_gf,
                                            lam, p_g1, p_g2, p_gf);
    tmerge_kernel<<<dim3(3*D_/32, D_/32, L_), t328>>>(Wqkv, d_Wqkv, lam, p_WqkvT,
                     D_, 3*D_, (size_t)L_*D_*3*D_);

    for (int l = 0; l < L_; l++){
        // attn (bf16 path)
        ln_kernel<<<N_/8,256>>>(p_x, p_g1 + l*D_, p_a);
        hgemm<0,0,1><<<dim3(N_/128, 3*D_/128), 256>>>(N_, 3*D_, D_, p_a,
                         p_WqkvT + (size_t)l*3*D_*D_, nullptr, p_qkvh);
        flash_attn<<<dim3(S_/128, B_*H_), 256>>>(p_qkvh, p_o);
        if (l == 0) cudaStreamWaitEvent(0, g_ss.join, 0);   // W merges ready
        hgemm<0,1,0><<<dim3(N_/128, D_/128), 256>>>(N_, D_, D_, p_o,
                         p_WoT + (size_t)l*D_*D_, p_x, p_x);
        // ffn (fp8 path)
        ln_f8_kernel<<<N_/8,256>>>(p_x, p_g2 + l*D_, p_af8);
        f8gemm<1,0,2><<<dim3(N_/128, DFF_/128), 256>>>(D_/2, DFF_,
            (const bf16*)p_af8, (const bf16*)(p_W18 + (size_t)l*DFF_*D_/4),
            nullptr, p_ff8, 1.f/1024.f, 16.f);
        f8gemm<0,1,0><<<dim3(N_/128, D_/128), 256>>>(DFF_/2, D_,
            (const bf16*)p_ff8, (const bf16*)(p_W28 + (size_t)l*D_*DFF_/4),
            p_x, p_x, 1.f/4096.f, 1.f);
    }

    // ---- head: fp8 logits GEMM with fused logsumexp ----
    ln_f8_kernel<<<N_/8,256>>>(p_x, p_gf, p_af8);
    cudaStreamWaitEvent(0, g_ss.join2, 0);                  // emb merge ready
    f8gemm_lse<<<dim3(N_/128, V_/128), 256>>>(D_/2,
        (const bf16*)p_af8, (const bf16*)p_embf8, labels, p_part, p_tgt);
    nll_final<<<N_,256>>>(p_part, p_tgt, p_nll);
    final_reduce<<<1,256>>>(p_nll, (float*)d_out);
}